// round 6
// baseline (speedup 1.0000x reference)
#include <cuda_runtime.h>
#include <cuda_bf16.h>
#include <math.h>

// ---------------- problem constants ----------------
#define D_MODEL   768
#define D_STATE   64
#define D_CONV    4
#define HEADDIM   64
#define D_INNER   1536
#define NHEADS    24
#define CONV_DIM  1664          // D_INNER + 2*D_STATE
#define D_IN_PROJ 3224          // 2*D_INNER + 2*D_STATE + NHEADS
#define BSZ       2
#define SEQ       512
#define NTOK      (BSZ*SEQ)     // 1024
#define EPS       1e-5f
#define D_FF      3072

// ---------------- scratch (device globals; no allocation allowed) ------------
__device__ float g_xn   [NTOK * D_MODEL];          // LN1 output
__device__ float g_zx   [NTOK * D_IN_PROJ];        // in_proj output
__device__ float g_dt   [NTOK * NHEADS];           // softplus(dt + bias)
__device__ float g_dA   [NTOK * NHEADS];           // exp(-exp(A_log)*dt)
__device__ float g_conv [2 * NTOK * CONV_DIM];     // conv+silu, per direction
__device__ float g_y    [2 * NTOK * D_INNER];      // scan output (orig coords)
__device__ float g_ysum [NTOK * D_INNER];          // gated+normed fwd+bwd
__device__ float g_mp   [NTOK * D_MODEL];          // out_f + out_b
__device__ float g_m    [NTOK * D_MODEL];          // LN2 output
__device__ float g_ff1  [NTOK * D_FF];             // gelu(m@W1+b1)

// ---------------- small device helpers ----------------
__device__ __forceinline__ float sigmoidf_(float x) { return 1.0f / (1.0f + __expf(-x)); }
__device__ __forceinline__ float siluf_(float x)    { return x * sigmoidf_(x); }
__device__ __forceinline__ float softplusf_(float x){ return (x > 20.0f) ? x : log1pf(expf(x)); }
__device__ __forceinline__ float geluf_(float x)    { return 0.5f * x * (1.0f + erff(x * 0.70710678118654752f)); }

// block reduction over 256 threads (sum)
__device__ __forceinline__ float block_sum_256(float v, float* sh) {
    #pragma unroll
    for (int o = 16; o; o >>= 1) v += __shfl_xor_sync(0xffffffffu, v, o);
    if ((threadIdx.x & 31) == 0) sh[threadIdx.x >> 5] = v;
    __syncthreads();
    float s = (threadIdx.x < 8) ? sh[threadIdx.x] : 0.0f;
    if (threadIdx.x < 8) {
        #pragma unroll
        for (int o = 4; o; o >>= 1) s += __shfl_xor_sync(0xffu, s, o);
        if (threadIdx.x == 0) sh[0] = s;
    }
    __syncthreads();
    float r = sh[0];
    __syncthreads();
    return r;
}

// ---------------- layernorm: 1 block / token, 256 threads, D=768 -------------
__global__ __launch_bounds__(256) void ln_kernel(
    const float* __restrict__ x, const float* __restrict__ w,
    const float* __restrict__ b, float* __restrict__ out)
{
    __shared__ float sh[8];
    const int tok = blockIdx.x;
    const float* xi = x + (size_t)tok * D_MODEL;
    float v[3];
    #pragma unroll
    for (int i = 0; i < 3; i++) v[i] = xi[threadIdx.x + i * 256];
    float s = v[0] + v[1] + v[2];
    s = block_sum_256(s, sh);
    const float mu = s * (1.0f / D_MODEL);
    float c[3], sq = 0.0f;
    #pragma unroll
    for (int i = 0; i < 3; i++) { c[i] = v[i] - mu; sq += c[i] * c[i]; }
    sq = block_sum_256(sq, sh);
    const float rstd = rsqrtf(sq * (1.0f / D_MODEL) + EPS);
    float* yo = out + (size_t)tok * D_MODEL;
    #pragma unroll
    for (int i = 0; i < 3; i++) {
        int idx = threadIdx.x + i * 256;
        yo[idx] = c[i] * rstd * w[idx] + b[idx];
    }
}

// ---------------- dt preprocessing ----------------
__global__ __launch_bounds__(256) void dt_kernel(
    const float* __restrict__ zx, const float* __restrict__ dt_bias,
    const float* __restrict__ A_log, float* __restrict__ dt_sp, float* __restrict__ dA)
{
    int idx = blockIdx.x * 256 + threadIdx.x;          // NTOK*NHEADS = 24576
    if (idx >= NTOK * NHEADS) return;
    int h = idx % NHEADS;
    int tok = idx / NHEADS;
    float v = zx[(size_t)tok * D_IN_PROJ + 3200 + h];  // dt columns are [3200, 3224)
    float sp = softplusf_(v + dt_bias[h]);
    dt_sp[idx] = sp;
    dA[idx] = __expf(-__expf(A_log[h]) * sp);
}

// ---------------- conv1d (+bias, silu), both directions ----------------
__global__ __launch_bounds__(256) void conv_kernel(
    const float* __restrict__ zx, const float* __restrict__ conv_w,
    const float* __restrict__ conv_b, float* __restrict__ out)
{
    long long idx = (long long)blockIdx.x * 256 + threadIdx.x;
    const long long total = 2LL * NTOK * CONV_DIM;
    if (idx >= total) return;
    int c = (int)(idx % CONV_DIM);
    long long r = idx / CONV_DIM;
    int t = (int)(r % SEQ);
    r /= SEQ;
    int b = (int)(r % BSZ);
    int dir = (int)(r / BSZ);
    const float4 w = *(const float4*)(conv_w + (size_t)c * 4);
    const float* base = zx + ((size_t)b * SEQ) * D_IN_PROJ + D_INNER + c;
    float acc = 0.0f;
    if (dir == 0) {
        if (t >= 3) acc += w.x * base[(size_t)(t - 3) * D_IN_PROJ];
        if (t >= 2) acc += w.y * base[(size_t)(t - 2) * D_IN_PROJ];
        if (t >= 1) acc += w.z * base[(size_t)(t - 1) * D_IN_PROJ];
        acc += w.w * base[(size_t)t * D_IN_PROJ];
    } else {
        if (t + 3 < SEQ) acc += w.x * base[(size_t)(t + 3) * D_IN_PROJ];
        if (t + 2 < SEQ) acc += w.y * base[(size_t)(t + 2) * D_IN_PROJ];
        if (t + 1 < SEQ) acc += w.z * base[(size_t)(t + 1) * D_IN_PROJ];
        acc += w.w * base[(size_t)t * D_IN_PROJ];
    }
    acc += conv_b[c];
    out[idx] = siluf_(acc);
}

// ---------------- SSM scan v2 ------------------------------------------------
// 1 block / (head, batch, dir); 128 threads: p = tid&63 (headdim lane),
// g = tid>>6 selects half of the 64 states. Each thread holds 32 h-states.
// Distance-2 register prefetch of B/C/x/dt/dA; double-buffered B/C staging.
__global__ __launch_bounds__(128) void scan_kernel(
    const float* __restrict__ conv, const float* __restrict__ dt_sp,
    const float* __restrict__ dA_g, const float* __restrict__ D_param,
    float* __restrict__ y_out)
{
    const int hd  = blockIdx.x;
    const int b   = blockIdx.y;
    const int dir = blockIdx.z;
    const int tid = threadIdx.x;
    const int p   = tid & 63;
    const int g   = tid >> 6;                 // 0 or 1
    const float Dh = D_param[hd];

    float h[32];
    #pragma unroll
    for (int n = 0; n < 32; n++) h[n] = 0.0f;

    __shared__ __align__(16) float Bs[2][64];
    __shared__ __align__(16) float Cs[2][64];
    __shared__ float part[64];

    const size_t seq_base = (size_t)(dir * BSZ + b) * SEQ;

    // prefetch slots for steps step, step+1 (indexed by step&1)
    float pBC[2], pX[2], pDT[2], pDA[2];
    #pragma unroll
    for (int i = 0; i < 2; i++) {
        const int s = dir ? (SEQ - 1 - i) : i;
        const float* row = conv + (seq_base + s) * CONV_DIM;
        pBC[i] = row[D_INNER + g * D_STATE + p];
        pX[i]  = row[hd * HEADDIM + p];
        const int th = (b * SEQ + s) * NHEADS + hd;
        pDT[i] = dt_sp[th];
        pDA[i] = dA_g[th];
    }

    for (int step = 0; step < SEQ; step++) {
        const int buf = step & 1;
        const int s = dir ? (SEQ - 1 - step) : step;

        // consume slot into locals, stage B/C into smem
        const float xv  = pX[buf];
        const float dtv = pDT[buf];
        const float dav = pDA[buf];
        if (g == 0) Bs[buf][p] = pBC[buf];
        else        Cs[buf][p] = pBC[buf];

        // prefetch step+2 into this slot (clamped dummy at the end)
        {
            const int s2 = (step + 2 < SEQ) ? step + 2 : SEQ - 1;
            const int ss = dir ? (SEQ - 1 - s2) : s2;
            const float* row2 = conv + (seq_base + ss) * CONV_DIM;
            pBC[buf] = row2[D_INNER + g * D_STATE + p];
            pX[buf]  = row2[hd * HEADDIM + p];
            const int th2 = (b * SEQ + ss) * NHEADS + hd;
            pDT[buf] = dt_sp[th2];
            pDA[buf] = dA_g[th2];
        }
        __syncthreads();

        const float coeff = dtv * xv;
        const float4* B4 = (const float4*)(Bs[buf] + g * 32);
        const float4* C4 = (const float4*)(Cs[buf] + g * 32);
        float a0 = 0.f, a1 = 0.f, a2 = 0.f, a3 = 0.f;
        #pragma unroll
        for (int q = 0; q < 8; q++) {
            float4 bb = B4[q];
            float4 cc = C4[q];
            h[4*q+0] = fmaf(dav, h[4*q+0], coeff * bb.x);  a0 = fmaf(h[4*q+0], cc.x, a0);
            h[4*q+1] = fmaf(dav, h[4*q+1], coeff * bb.y);  a1 = fmaf(h[4*q+1], cc.y, a1);
            h[4*q+2] = fmaf(dav, h[4*q+2], coeff * bb.z);  a2 = fmaf(h[4*q+2], cc.z, a2);
            h[4*q+3] = fmaf(dav, h[4*q+3], coeff * bb.w);  a3 = fmaf(h[4*q+3], cc.w, a3);
        }
        const float acc = (a0 + a1) + (a2 + a3);
        if (g) part[p] = acc;
        __syncthreads();
        if (!g) {
            y_out[(seq_base + s) * D_INNER + hd * HEADDIM + p] = acc + part[p] + Dh * xv;
        }
    }
}

// ---------------- gate (silu(z)) + RMSNorm per direction, then sum -----------
__global__ __launch_bounds__(256) void gate_kernel(
    const float* __restrict__ y, const float* __restrict__ zx,
    const float* __restrict__ norm_w, float* __restrict__ ysum)
{
    __shared__ float sh[8];
    const int t = blockIdx.x;
    const int b = blockIdx.y;
    const size_t tok = (size_t)b * SEQ + t;
    const float* zrow = zx + tok * D_IN_PROJ;          // z is [0, D_INNER)
    const float* yf = y + tok * D_INNER;
    const float* yb = y + ((size_t)BSZ * SEQ + tok) * D_INNER;

    float gf[6], gb[6];
    float sf = 0.0f, sb = 0.0f;
    #pragma unroll
    for (int i = 0; i < 6; i++) {
        int c = threadIdx.x + i * 256;
        float g = siluf_(zrow[c]);
        gf[i] = yf[c] * g;  sf += gf[i] * gf[i];
        gb[i] = yb[c] * g;  sb += gb[i] * gb[i];
    }
    sf = block_sum_256(sf, sh);
    sb = block_sum_256(sb, sh);
    const float scf = rsqrtf(sf * (1.0f / D_INNER) + EPS);
    const float scb = rsqrtf(sb * (1.0f / D_INNER) + EPS);
    float* o = ysum + tok * D_INNER;
    #pragma unroll
    for (int i = 0; i < 6; i++) {
        int c = threadIdx.x + i * 256;
        o[c] = (gf[i] * scf + gb[i] * scb) * norm_w[c];
    }
}

// =============================================================================
// GEMM BIG: C[M,N] = A[M,K] @ Bw[N,K]^T
// BM=128, BN=128, BK=8, 256 threads, 8x8 per thread, double-buffered smem.
// Requires M % 128 == 0 and K % 8 == 0 (true for all uses). N may be ragged.
// EPI 0: plain   EPI 1: gelu(x+bias)
// =============================================================================
template<int EPI>
__global__ __launch_bounds__(256) void gemm128_kernel(
    const float* __restrict__ A, const float* __restrict__ Bw,
    const float* __restrict__ bias, float* __restrict__ C,
    int M, int N, int K)
{
    __shared__ __align__(16) float As[2][8][132];
    __shared__ __align__(16) float Bs[2][8][132];

    const int tid = threadIdx.x;
    const int m0 = blockIdx.y * 128;
    const int n0 = blockIdx.x * 128;

    const int lrow = tid >> 1;        // 0..127
    const int lk4  = (tid & 1) * 4;   // 0 or 4

    const int tx = tid & 15;          // n sub-tile: tx*8
    const int ty = tid >> 4;          // m sub-tile: ty*8

    float acc[8][8];
    #pragma unroll
    for (int i = 0; i < 8; i++)
        #pragma unroll
        for (int j = 0; j < 8; j++) acc[i][j] = 0.0f;

    const float* Aptr = A + (size_t)(m0 + lrow) * K + lk4;   // M divisible -> no guard
    const int    brow = n0 + lrow;
    const float* Bptr = Bw + (size_t)brow * K + lk4;
    const bool   bok  = (brow < N);

    float4 aV = *(const float4*)(Aptr);
    float4 bV = bok ? *(const float4*)(Bptr) : make_float4(0.f, 0.f, 0.f, 0.f);

    int buf = 0;
    {
        As[0][lk4+0][lrow] = aV.x; As[0][lk4+1][lrow] = aV.y;
        As[0][lk4+2][lrow] = aV.z; As[0][lk4+3][lrow] = aV.w;
        Bs[0][lk4+0][lrow] = bV.x; Bs[0][lk4+1][lrow] = bV.y;
        Bs[0][lk4+2][lrow] = bV.z; Bs[0][lk4+3][lrow] = bV.w;
    }
    __syncthreads();

    for (int k0 = 8; k0 < K; k0 += 8) {
        aV = *(const float4*)(Aptr + k0);
        bV = bok ? *(const float4*)(Bptr + k0) : make_float4(0.f, 0.f, 0.f, 0.f);

        #pragma unroll
        for (int k = 0; k < 8; k++) {
            float4 a0 = *(const float4*)&As[buf][k][ty * 8];
            float4 a1 = *(const float4*)&As[buf][k][ty * 8 + 4];
            float4 b0 = *(const float4*)&Bs[buf][k][tx * 8];
            float4 b1 = *(const float4*)&Bs[buf][k][tx * 8 + 4];
            float ar[8] = {a0.x,a0.y,a0.z,a0.w,a1.x,a1.y,a1.z,a1.w};
            float br[8] = {b0.x,b0.y,b0.z,b0.w,b1.x,b1.y,b1.z,b1.w};
            #pragma unroll
            for (int i = 0; i < 8; i++)
                #pragma unroll
                for (int j = 0; j < 8; j++)
                    acc[i][j] = fmaf(ar[i], br[j], acc[i][j]);
        }
        buf ^= 1;
        As[buf][lk4+0][lrow] = aV.x; As[buf][lk4+1][lrow] = aV.y;
        As[buf][lk4+2][lrow] = aV.z; As[buf][lk4+3][lrow] = aV.w;
        Bs[buf][lk4+0][lrow] = bV.x; Bs[buf][lk4+1][lrow] = bV.y;
        Bs[buf][lk4+2][lrow] = bV.z; Bs[buf][lk4+3][lrow] = bV.w;
        __syncthreads();
    }
    #pragma unroll
    for (int k = 0; k < 8; k++) {
        float4 a0 = *(const float4*)&As[buf][k][ty * 8];
        float4 a1 = *(const float4*)&As[buf][k][ty * 8 + 4];
        float4 b0 = *(const float4*)&Bs[buf][k][tx * 8];
        float4 b1 = *(const float4*)&Bs[buf][k][tx * 8 + 4];
        float ar[8] = {a0.x,a0.y,a0.z,a0.w,a1.x,a1.y,a1.z,a1.w};
        float br[8] = {b0.x,b0.y,b0.z,b0.w,b1.x,b1.y,b1.z,b1.w};
        #pragma unroll
        for (int i = 0; i < 8; i++)
            #pragma unroll
            for (int j = 0; j < 8; j++)
                acc[i][j] = fmaf(ar[i], br[j], acc[i][j]);
    }

    // epilogue
    if (n0 + 128 <= N) {
        #pragma unroll
        for (int i = 0; i < 8; i++) {
            const int m = m0 + ty * 8 + i;
            float* crow = C + (size_t)m * N + n0 + tx * 8;
            #pragma unroll
            for (int jj = 0; jj < 2; jj++) {
                float4 v;
                v.x = acc[i][jj*4+0]; v.y = acc[i][jj*4+1];
                v.z = acc[i][jj*4+2]; v.w = acc[i][jj*4+3];
                if (EPI == 1) {
                    const float* bi = bias + n0 + tx * 8 + jj * 4;
                    v.x = geluf_(v.x + bi[0]); v.y = geluf_(v.y + bi[1]);
                    v.z = geluf_(v.z + bi[2]); v.w = geluf_(v.w + bi[3]);
                }
                *(float4*)(crow + jj * 4) = v;
            }
        }
    } else {
        #pragma unroll
        for (int i = 0; i < 8; i++) {
            const int m = m0 + ty * 8 + i;
            #pragma unroll
            for (int j = 0; j < 8; j++) {
                const int n = n0 + tx * 8 + j;
                if (n < N) {
                    float v = acc[i][j];
                    if (EPI == 1) v = geluf_(v + bias[n]);
                    C[(size_t)m * N + n] = v;
                }
            }
        }
    }
}

// =============================================================================
// GEMM MED: C[M,N] = A[M,K] @ Bw[N,K]^T
// BM=64, BN=64, BK=16, 128 threads, 8x4 per thread, double-buffered smem.
// Requires M%64==0, N%64==0, K%16==0 (true for out_proj / ff2).
// EPI 0: plain   EPI 2: x + bias + resid
// =============================================================================
template<int EPI>
__global__ __launch_bounds__(128) void gemm64_kernel(
    const float* __restrict__ A, const float* __restrict__ Bw,
    const float* __restrict__ bias, const float* __restrict__ resid,
    float* __restrict__ C, int M, int N, int K)
{
    __shared__ __align__(16) float As[2][16][68];
    __shared__ __align__(16) float Bs[2][16][68];

    const int tid = threadIdx.x;
    const int m0 = blockIdx.y * 64;
    const int n0 = blockIdx.x * 64;

    const int lrow = tid >> 1;        // 0..63
    const int lk8  = (tid & 1) * 8;   // 0 or 8

    const int tx = tid & 15;          // n: tx*4
    const int ty = tid >> 4;          // m: ty*8  (0..7)

    float acc[8][4];
    #pragma unroll
    for (int i = 0; i < 8; i++)
        #pragma unroll
        for (int j = 0; j < 4; j++) acc[i][j] = 0.0f;

    const float* Aptr = A  + (size_t)(m0 + lrow) * K + lk8;
    const float* Bptr = Bw + (size_t)(n0 + lrow) * K + lk8;

    float4 aV0 = *(const float4*)(Aptr);
    float4 aV1 = *(const float4*)(Aptr + 4);
    float4 bV0 = *(const float4*)(Bptr);
    float4 bV1 = *(const float4*)(Bptr + 4);

    int buf = 0;
    {
        As[0][lk8+0][lrow]=aV0.x; As[0][lk8+1][lrow]=aV0.y; As[0][lk8+2][lrow]=aV0.z; As[0][lk8+3][lrow]=aV0.w;
        As[0][lk8+4][lrow]=aV1.x; As[0][lk8+5][lrow]=aV1.y; As[0][lk8+6][lrow]=aV1.z; As[0][lk8+7][lrow]=aV1.w;
        Bs[0][lk8+0][lrow]=bV0.x; Bs[0][lk8+1][lrow]=bV0.y; Bs[0][lk8+2][lrow]=bV0.z; Bs[0][lk8+3][lrow]=bV0.w;
        Bs[0][lk8+4][lrow]=bV1.x; Bs[0][lk8+5][lrow]=bV1.y; Bs[0][lk8+6][lrow]=bV1.z; Bs[0][lk8+7][lrow]=bV1.w;
    }
    __syncthreads();

    for (int k0 = 16; k0 < K; k0 += 16) {
        aV0 = *(const float4*)(Aptr + k0);
        aV1 = *(const float4*)(Aptr + k0 + 4);
        bV0 = *(const float4*)(Bptr + k0);
        bV1 = *(const float4*)(Bptr + k0 + 4);

        #pragma unroll
        for (int k = 0; k < 16; k++) {
            float4 a0 = *(const float4*)&As[buf][k][ty * 8];
            float4 a1 = *(const float4*)&As[buf][k][ty * 8 + 4];
            float4 b0 = *(const float4*)&Bs[buf][k][tx * 4];
            float ar[8] = {a0.x,a0.y,a0.z,a0.w,a1.x,a1.y,a1.z,a1.w};
            float br[4] = {b0.x,b0.y,b0.z,b0.w};
            #pragma unroll
            for (int i = 0; i < 8; i++)
                #pragma unroll
                for (int j = 0; j < 4; j++)
                    acc[i][j] = fmaf(ar[i], br[j], acc[i][j]);
        }
        buf ^= 1;
        As[buf][lk8+0][lrow]=aV0.x; As[buf][lk8+1][lrow]=aV0.y; As[buf][lk8+2][lrow]=aV0.z; As[buf][lk8+3][lrow]=aV0.w;
        As[buf][lk8+4][lrow]=aV1.x; As[buf][lk8+5][lrow]=aV1.y; As[buf][lk8+6][lrow]=aV1.z; As[buf][lk8+7][lrow]=aV1.w;
        Bs[buf][lk8+0][lrow]=bV0.x; Bs[buf][lk8+1][lrow]=bV0.y; Bs[buf][lk8+2][lrow]=bV0.z; Bs[buf][lk8+3][lrow]=bV0.w;
        Bs[buf][lk8+4][lrow]=bV1.x; Bs[buf][lk8+5][lrow]=bV1.y; Bs[buf][lk8+6][lrow]=bV1.z; Bs[buf][lk8+7][lrow]=bV1.w;
        __syncthreads();
    }
    #pragma unroll
    for (int k = 0; k < 16; k++) {
        float4 a0 = *(const float4*)&As[buf][k][ty * 8];
        float4 a1 = *(const float4*)&As[buf][k][ty * 8 + 4];
        float4 b0 = *(const float4*)&Bs[buf][k][tx * 4];
        float ar[8] = {a0.x,a0.y,a0.z,a0.w,a1.x,a1.y,a1.z,a1.w};
        float br[4] = {b0.x,b0.y,b0.z,b0.w};
        #pragma unroll
        for (int i = 0; i < 8; i++)
            #pragma unroll
            for (int j = 0; j < 4; j++)
                acc[i][j] = fmaf(ar[i], br[j], acc[i][j]);
    }

    #pragma unroll
    for (int i = 0; i < 8; i++) {
        const int m = m0 + ty * 8 + i;
        const int n = n0 + tx * 4;
        float4 v;
        v.x = acc[i][0]; v.y = acc[i][1]; v.z = acc[i][2]; v.w = acc[i][3];
        if (EPI == 2) {
            const float* bi = bias + n;
            const float* rr = resid + (size_t)m * N + n;
            v.x += bi[0] + rr[0]; v.y += bi[1] + rr[1];
            v.z += bi[2] + rr[2]; v.w += bi[3] + rr[3];
        }
        *(float4*)(C + (size_t)m * N + n) = v;
    }
}

// ---------------- launch ----------------
extern "C" void kernel_launch(void* const* d_in, const int* in_sizes, int n_in,
                              void* d_out, int out_size)
{
    const float* x          = (const float*)d_in[0];
    const float* in_proj_w  = (const float*)d_in[1];
    const float* conv_w     = (const float*)d_in[2];
    const float* conv_b     = (const float*)d_in[3];
    const float* dt_bias    = (const float*)d_in[4];
    const float* A_log      = (const float*)d_in[5];
    const float* D_param    = (const float*)d_in[6];
    const float* norm_w     = (const float*)d_in[7];
    const float* out_proj_w = (const float*)d_in[8];
    const float* ln1_w      = (const float*)d_in[9];
    const float* ln1_b      = (const float*)d_in[10];
    const float* ln2_w      = (const float*)d_in[11];
    const float* ln2_b      = (const float*)d_in[12];
    const float* ff_w1      = (const float*)d_in[13];
    const float* ff_b1      = (const float*)d_in[14];
    const float* ff_w2      = (const float*)d_in[15];
    const float* ff_b2      = (const float*)d_in[16];
    float* out = (float*)d_out;

    float *p_xn, *p_zx, *p_dt, *p_dA, *p_conv, *p_y, *p_ysum, *p_mp, *p_m, *p_ff1;
    cudaGetSymbolAddress((void**)&p_xn,   g_xn);
    cudaGetSymbolAddress((void**)&p_zx,   g_zx);
    cudaGetSymbolAddress((void**)&p_dt,   g_dt);
    cudaGetSymbolAddress((void**)&p_dA,   g_dA);
    cudaGetSymbolAddress((void**)&p_conv, g_conv);
    cudaGetSymbolAddress((void**)&p_y,    g_y);
    cudaGetSymbolAddress((void**)&p_ysum, g_ysum);
    cudaGetSymbolAddress((void**)&p_mp,   g_mp);
    cudaGetSymbolAddress((void**)&p_m,    g_m);
    cudaGetSymbolAddress((void**)&p_ff1,  g_ff1);

    // 1) LN1
    ln_kernel<<<NTOK, 256>>>(x, ln1_w, ln1_b, p_xn);
    // 2) in_proj: [1024,3224] = xn @ Wᵀ  (shared by both directions)
    gemm128_kernel<0><<<dim3((D_IN_PROJ + 127) / 128, NTOK / 128), 256>>>(
        p_xn, in_proj_w, nullptr, p_zx, NTOK, D_IN_PROJ, D_MODEL);
    // 3) dt preprocessing
    dt_kernel<<<(NTOK * NHEADS + 255) / 256, 256>>>(p_zx, dt_bias, A_log, p_dt, p_dA);
    // 4) conv + silu (both directions)
    {
        long long total = 2LL * NTOK * CONV_DIM;
        conv_kernel<<<(unsigned)((total + 255) / 256), 256>>>(p_zx, conv_w, conv_b, p_conv);
    }
    // 5) SSM scan (both directions)
    scan_kernel<<<dim3(NHEADS, BSZ, 2), 128>>>(p_conv, p_dt, p_dA, D_param, p_y);
    // 6) gate + rmsnorm + combine directions
    gate_kernel<<<dim3(SEQ, BSZ), 256>>>(p_y, p_zx, norm_w, p_ysum);
    // 7) out_proj (single GEMM covers out_f + out_b)
    gemm64_kernel<0><<<dim3(D_MODEL / 64, NTOK / 64), 128>>>(
        p_ysum, out_proj_w, nullptr, nullptr, p_mp, NTOK, D_MODEL, D_INNER);
    // 8) LN2
    ln_kernel<<<NTOK, 256>>>(p_mp, ln2_w, ln2_b, p_m);
    // 9) FFN1 (+bias, gelu)
    gemm128_kernel<1><<<dim3(D_FF / 128, NTOK / 128), 256>>>(
        p_m, ff_w1, ff_b1, p_ff1, NTOK, D_FF, D_MODEL);
    // 10) FFN2 (+bias, +residual x) -> d_out
    gemm64_kernel<2><<<dim3(D_MODEL / 64, NTOK / 64), 128>>>(
        p_ff1, ff_w2, ff_b2, x, out, NTOK, D_MODEL, D_FF);
}

// round 8
// speedup vs baseline: 1.8076x; 1.8076x over previous
#include <cuda_runtime.h>
#include <cuda_bf16.h>
#include <math.h>
#include <stdint.h>

// ---------------- problem constants ----------------
#define D_MODEL   768
#define D_STATE   64
#define D_CONV    4
#define HEADDIM   64
#define D_INNER   1536
#define NHEADS    24
#define CONV_DIM  1664          // D_INNER + 2*D_STATE
#define D_IN_PROJ 3224          // 2*D_INNER + 2*D_STATE + NHEADS
#define BSZ       2
#define SEQ       512
#define NTOK      (BSZ*SEQ)     // 1024
#define EPS       1e-5f
#define D_FF      3072
#define NPAD_INPROJ 3328        // D_IN_PROJ padded to 128

// ---------------- scratch (device globals; no allocation allowed) ------------
__device__ float g_zx   [NTOK * D_IN_PROJ];
__device__ float g_dt   [NTOK * NHEADS];
__device__ float g_dA   [NTOK * NHEADS];
__device__ float g_conv [2 * NTOK * CONV_DIM];
__device__ float g_y    [2 * NTOK * D_INNER];
__device__ float g_mp   [NTOK * D_MODEL];

// bf16 split buffers
__device__ __nv_bfloat16 g_w1h[NPAD_INPROJ * D_MODEL], g_w1l[NPAD_INPROJ * D_MODEL];
__device__ __nv_bfloat16 g_w2h[D_MODEL * D_INNER],     g_w2l[D_MODEL * D_INNER];
__device__ __nv_bfloat16 g_w3h[D_FF * D_MODEL],        g_w3l[D_FF * D_MODEL];
__device__ __nv_bfloat16 g_w4h[D_MODEL * D_FF],        g_w4l[D_MODEL * D_FF];
__device__ __nv_bfloat16 g_a0h[NTOK * D_INNER],        g_a0l[NTOK * D_INNER];
__device__ __nv_bfloat16 g_a1h[NTOK * D_FF],           g_a1l[NTOK * D_FF];

// ---------------- small device helpers ----------------
__device__ __forceinline__ float sigmoidf_(float x) { return 1.0f / (1.0f + __expf(-x)); }
__device__ __forceinline__ float siluf_(float x)    { return x * sigmoidf_(x); }
__device__ __forceinline__ float softplusf_(float x){ return (x > 20.0f) ? x : log1pf(expf(x)); }
__device__ __forceinline__ float geluf_(float x)    { return 0.5f * x * (1.0f + erff(x * 0.70710678118654752f)); }

__device__ __forceinline__ float block_sum_256(float v, float* sh) {
    #pragma unroll
    for (int o = 16; o; o >>= 1) v += __shfl_xor_sync(0xffffffffu, v, o);
    if ((threadIdx.x & 31) == 0) sh[threadIdx.x >> 5] = v;
    __syncthreads();
    float s = (threadIdx.x < 8) ? sh[threadIdx.x] : 0.0f;
    if (threadIdx.x < 8) {
        #pragma unroll
        for (int o = 4; o; o >>= 1) s += __shfl_xor_sync(0xffu, s, o);
        if (threadIdx.x == 0) sh[0] = s;
    }
    __syncthreads();
    float r = sh[0];
    __syncthreads();
    return r;
}

__device__ __forceinline__ uint32_t smem_u32(const void* p) {
    uint32_t a;
    asm("{ .reg .u64 t; cvta.to.shared.u64 t, %1; cvt.u32.u64 %0, t; }" : "=r"(a) : "l"(p));
    return a;
}

#define LDMX4(R0,R1,R2,R3,ADDR) \
    asm volatile("ldmatrix.sync.aligned.m8n8.x4.shared.b16 {%0,%1,%2,%3}, [%4];" \
        : "=r"(R0),"=r"(R1),"=r"(R2),"=r"(R3) : "r"(ADDR))

#define MMA16816(D,A,B) \
    asm volatile("mma.sync.aligned.m16n8k16.row.col.f32.bf16.bf16.f32 " \
        "{%0,%1,%2,%3},{%4,%5,%6,%7},{%8,%9},{%0,%1,%2,%3};" \
        : "+f"((D)[0]),"+f"((D)[1]),"+f"((D)[2]),"+f"((D)[3]) \
        : "r"((A)[0]),"r"((A)[1]),"r"((A)[2]),"r"((A)[3]), "r"((B)[0]),"r"((B)[1]))

__device__ __forceinline__ uint32_t packbf(__nv_bfloat16 a, __nv_bfloat16 b) {
    return ((uint32_t)__bfloat16_as_ushort(b) << 16) | __bfloat16_as_ushort(a);
}

// =============================================================================
// Weight fp32 -> bf16 hi/lo split (with row padding to Npad)
// =============================================================================
__global__ __launch_bounds__(256) void convw_kernel(
    const float* __restrict__ W, __nv_bfloat16* __restrict__ hi,
    __nv_bfloat16* __restrict__ lo, int Ntrue, int Npad, int K)
{
    int i4 = blockIdx.x * 256 + threadIdx.x;
    int total = (Npad * K) >> 2;
    if (i4 >= total) return;
    size_t e = (size_t)i4 * 4;
    int n = (int)(e / (size_t)K);
    float4 v = make_float4(0.f, 0.f, 0.f, 0.f);
    if (n < Ntrue) v = *(const float4*)(W + e);
    __nv_bfloat16 h0 = __float2bfloat16(v.x), h1 = __float2bfloat16(v.y);
    __nv_bfloat16 h2 = __float2bfloat16(v.z), h3 = __float2bfloat16(v.w);
    __nv_bfloat16 l0 = __float2bfloat16(v.x - __bfloat162float(h0));
    __nv_bfloat16 l1 = __float2bfloat16(v.y - __bfloat162float(h1));
    __nv_bfloat16 l2 = __float2bfloat16(v.z - __bfloat162float(h2));
    __nv_bfloat16 l3 = __float2bfloat16(v.w - __bfloat162float(h3));
    *(uint2*)(hi + e) = make_uint2(packbf(h0,h1), packbf(h2,h3));
    *(uint2*)(lo + e) = make_uint2(packbf(l0,l1), packbf(l2,l3));
}

// =============================================================================
// mma.sync split-bf16 GEMM: C[M,N] = A[M,K] @ W[N,K]^T   (fp32-equivalent)
// BM=128, BN in {128,64}; 256 threads; KC=32 double-buffered smem (pad-40 rows)
// EPI 0: C=acc (fp32)   EPI 1: gelu(acc+bias) -> Chi/Clo bf16 split
// EPI 2: C = acc + bias + resid (fp32)
// Requires M%128==0, K%32==0; W padded to gridDim.x*BN rows; N guard in epilogue.
// =============================================================================
template<int BN, int EPI>
__global__ __launch_bounds__(256) void mma_gemm_kernel(
    const __nv_bfloat16* __restrict__ Ahi, const __nv_bfloat16* __restrict__ Alo,
    const __nv_bfloat16* __restrict__ Whi, const __nv_bfloat16* __restrict__ Wlo,
    const float* __restrict__ bias, const float* __restrict__ resid,
    float* __restrict__ C, __nv_bfloat16* __restrict__ Chi, __nv_bfloat16* __restrict__ Clo,
    int M, int N, int K)
{
    constexpr int NJ     = BN / 32;       // n8 tiles per warp
    constexpr int NBCP   = BN / 64;       // uint4 copies/thread per B tile
    constexpr int ABYTES = 128 * 80;
    constexpr int BBYTES = BN * 80;
    constexpr int OFF_AL = ABYTES;
    constexpr int OFF_BH = 2 * ABYTES;
    constexpr int BUF    = 2 * ABYTES + 2 * BBYTES;

    extern __shared__ char sm[];
    const uint32_t sb = smem_u32(sm);

    const int tid  = threadIdx.x;
    const int wid  = tid >> 5, lane = tid & 31;
    const int m0   = blockIdx.y * 128, n0 = blockIdx.x * BN;
    const int warp_m = (wid >> 2) * 64;
    const int warp_n = (wid & 3) * (BN / 4);

    const int k4 = K >> 3;   // uint4 per row
    const uint4* gAh = (const uint4*)(Ahi + (size_t)m0 * K);
    const uint4* gAl = (const uint4*)(Alo + (size_t)m0 * K);
    const uint4* gBh = (const uint4*)(Whi + (size_t)n0 * K);
    const uint4* gBl = (const uint4*)(Wlo + (size_t)n0 * K);

    const int cr = tid >> 2, cq = tid & 3;

    float acc[4][NJ][4];
    #pragma unroll
    for (int mi = 0; mi < 4; mi++)
        #pragma unroll
        for (int nj = 0; nj < NJ; nj++)
            #pragma unroll
            for (int t = 0; t < 4; t++) acc[mi][nj][t] = 0.0f;

    uint4 vah[2], val[2], vbh[NBCP], vbl[NBCP];

    auto LOADC = [&](int kc) {
        const int kb = kc * 4;
        vah[0] = gAh[(size_t)cr * k4 + kb + cq];
        vah[1] = gAh[(size_t)(cr + 64) * k4 + kb + cq];
        val[0] = gAl[(size_t)cr * k4 + kb + cq];
        val[1] = gAl[(size_t)(cr + 64) * k4 + kb + cq];
        #pragma unroll
        for (int j = 0; j < NBCP; j++) {
            const int r = cr + j * 64;
            vbh[j] = gBh[(size_t)r * k4 + kb + cq];
            vbl[j] = gBl[(size_t)r * k4 + kb + cq];
        }
    };
    auto STOREC = [&](int b) {
        char* base = sm + b * BUF;
        *(uint4*)(base + (size_t)cr * 80 + cq * 16) = vah[0];
        *(uint4*)(base + (size_t)(cr + 64) * 80 + cq * 16) = vah[1];
        *(uint4*)(base + OFF_AL + (size_t)cr * 80 + cq * 16) = val[0];
        *(uint4*)(base + OFF_AL + (size_t)(cr + 64) * 80 + cq * 16) = val[1];
        #pragma unroll
        for (int j = 0; j < NBCP; j++) {
            const int r = cr + j * 64;
            *(uint4*)(base + OFF_BH + (size_t)r * 80 + cq * 16) = vbh[j];
            *(uint4*)(base + OFF_BH + BBYTES + (size_t)r * 80 + cq * 16) = vbl[j];
        }
    };

    const int r_a  = (lane & 7) + ((lane >> 3) & 1) * 8;
    const int ch_a = ((lane >> 4) & 1) * 8;
    const int rB   = lane & 7, jB = lane >> 3;
    const int n_b  = ((jB >> 1) << 3) + rB;
    const int kh_b = (jB & 1) << 3;

    auto COMPUTE = [&](int b) {
        const uint32_t Abase = sb + b * BUF;
        #pragma unroll
        for (int kk = 0; kk < 2; kk++) {
            uint32_t ah[4][4], al[4][4], bh[NJ][2], bl[NJ][2];
            #pragma unroll
            for (int mi = 0; mi < 4; mi++) {
                const uint32_t ad = Abase + (warp_m + mi * 16 + r_a) * 80 + (kk * 16 + ch_a) * 2;
                LDMX4(ah[mi][0], ah[mi][1], ah[mi][2], ah[mi][3], ad);
                LDMX4(al[mi][0], al[mi][1], al[mi][2], al[mi][3], ad + OFF_AL);
            }
            #pragma unroll
            for (int g = 0; g < NJ / 2; g++) {
                const uint32_t bd = Abase + OFF_BH + (warp_n + g * 16 + n_b) * 80 + (kk * 16 + kh_b) * 2;
                LDMX4(bh[2*g][0], bh[2*g][1], bh[2*g+1][0], bh[2*g+1][1], bd);
                LDMX4(bl[2*g][0], bl[2*g][1], bl[2*g+1][0], bl[2*g+1][1], bd + BBYTES);
            }
            #pragma unroll
            for (int mi = 0; mi < 4; mi++)
                #pragma unroll
                for (int nj = 0; nj < NJ; nj++) {
                    MMA16816(acc[mi][nj], ah[mi], bh[nj]);
                    MMA16816(acc[mi][nj], ah[mi], bl[nj]);
                    MMA16816(acc[mi][nj], al[mi], bh[nj]);
                }
        }
    };

    LOADC(0); STOREC(0); __syncthreads();
    const int NK = K >> 5;
    for (int kc = 0; kc < NK; kc++) {
        const int b = kc & 1;
        if (kc + 1 < NK) LOADC(kc + 1);
        COMPUTE(b);
        if (kc + 1 < NK) { STOREC(b ^ 1); __syncthreads(); }
    }

    // ---------------- epilogue ----------------
    const int lr = lane >> 2, lc = (lane & 3) * 2;
    #pragma unroll
    for (int mi = 0; mi < 4; mi++) {
        #pragma unroll
        for (int nj = 0; nj < NJ; nj++) {
            const int col = n0 + warp_n + nj * 8 + lc;
            if (col >= N) continue;
            #pragma unroll
            for (int hf = 0; hf < 2; hf++) {
                const int row = m0 + warp_m + mi * 16 + lr + hf * 8;
                float d0 = acc[mi][nj][hf * 2 + 0];
                float d1 = acc[mi][nj][hf * 2 + 1];
                if (EPI == 0) {
                    *(float2*)(C + (size_t)row * N + col) = make_float2(d0, d1);
                } else if (EPI == 1) {
                    float g0 = geluf_(d0 + bias[col]);
                    float g1 = geluf_(d1 + bias[col + 1]);
                    __nv_bfloat16 h0 = __float2bfloat16(g0), h1 = __float2bfloat16(g1);
                    __nv_bfloat16 l0 = __float2bfloat16(g0 - __bfloat162float(h0));
                    __nv_bfloat16 l1 = __float2bfloat16(g1 - __bfloat162float(h1));
                    *(__nv_bfloat162*)(Chi + (size_t)row * N + col) = __halves2bfloat162(h0, h1);
                    *(__nv_bfloat162*)(Clo + (size_t)row * N + col) = __halves2bfloat162(l0, l1);
                } else {
                    const float* rr = resid + (size_t)row * N + col;
                    *(float2*)(C + (size_t)row * N + col) =
                        make_float2(d0 + bias[col] + rr[0], d1 + bias[col + 1] + rr[1]);
                }
            }
        }
    }
}

// ---------------- layernorm -> bf16 hi/lo split output ----------------
__global__ __launch_bounds__(256) void ln_bf_kernel(
    const float* __restrict__ x, const float* __restrict__ w,
    const float* __restrict__ b, __nv_bfloat16* __restrict__ hi,
    __nv_bfloat16* __restrict__ lo)
{
    __shared__ float sh[8];
    const int tok = blockIdx.x;
    const float* xi = x + (size_t)tok * D_MODEL;
    float v[3];
    #pragma unroll
    for (int i = 0; i < 3; i++) v[i] = xi[threadIdx.x + i * 256];
    float s = v[0] + v[1] + v[2];
    s = block_sum_256(s, sh);
    const float mu = s * (1.0f / D_MODEL);
    float c[3], sq = 0.0f;
    #pragma unroll
    for (int i = 0; i < 3; i++) { c[i] = v[i] - mu; sq += c[i] * c[i]; }
    sq = block_sum_256(sq, sh);
    const float rstd = rsqrtf(sq * (1.0f / D_MODEL) + EPS);
    #pragma unroll
    for (int i = 0; i < 3; i++) {
        int idx = threadIdx.x + i * 256;
        float o = c[i] * rstd * w[idx] + b[idx];
        __nv_bfloat16 h = __float2bfloat16(o);
        hi[(size_t)tok * D_MODEL + idx] = h;
        lo[(size_t)tok * D_MODEL + idx] = __float2bfloat16(o - __bfloat162float(h));
    }
}

// ---------------- dt preprocessing ----------------
__global__ __launch_bounds__(256) void dt_kernel(
    const float* __restrict__ zx, const float* __restrict__ dt_bias,
    const float* __restrict__ A_log, float* __restrict__ dt_sp, float* __restrict__ dA)
{
    int idx = blockIdx.x * 256 + threadIdx.x;
    if (idx >= NTOK * NHEADS) return;
    int h = idx % NHEADS;
    int tok = idx / NHEADS;
    float v = zx[(size_t)tok * D_IN_PROJ + 3200 + h];
    float sp = softplusf_(v + dt_bias[h]);
    dt_sp[idx] = sp;
    dA[idx] = __expf(-__expf(A_log[h]) * sp);
}

// ---------------- conv1d (+bias, silu), both directions ----------------
__global__ __launch_bounds__(256) void conv_kernel(
    const float* __restrict__ zx, const float* __restrict__ conv_w,
    const float* __restrict__ conv_b, float* __restrict__ out)
{
    long long idx = (long long)blockIdx.x * 256 + threadIdx.x;
    const long long total = 2LL * NTOK * CONV_DIM;
    if (idx >= total) return;
    int c = (int)(idx % CONV_DIM);
    long long r = idx / CONV_DIM;
    int t = (int)(r % SEQ);
    r /= SEQ;
    int b = (int)(r % BSZ);
    int dir = (int)(r / BSZ);
    const float4 w = *(const float4*)(conv_w + (size_t)c * 4);
    const float* base = zx + ((size_t)b * SEQ) * D_IN_PROJ + D_INNER + c;
    float acc = 0.0f;
    if (dir == 0) {
        if (t >= 3) acc += w.x * base[(size_t)(t - 3) * D_IN_PROJ];
        if (t >= 2) acc += w.y * base[(size_t)(t - 2) * D_IN_PROJ];
        if (t >= 1) acc += w.z * base[(size_t)(t - 1) * D_IN_PROJ];
        acc += w.w * base[(size_t)t * D_IN_PROJ];
    } else {
        if (t + 3 < SEQ) acc += w.x * base[(size_t)(t + 3) * D_IN_PROJ];
        if (t + 2 < SEQ) acc += w.y * base[(size_t)(t + 2) * D_IN_PROJ];
        if (t + 1 < SEQ) acc += w.z * base[(size_t)(t + 1) * D_IN_PROJ];
        acc += w.w * base[(size_t)t * D_IN_PROJ];
    }
    acc += conv_b[c];
    out[idx] = siluf_(acc);
}

// ---------------- SSM scan: 1 block / (head, batch, dir); 64 threads ---------
__global__ __launch_bounds__(64) void scan_kernel(
    const float* __restrict__ conv, const float* __restrict__ dt_sp,
    const float* __restrict__ dA_g, const float* __restrict__ D_param,
    float* __restrict__ y_out)
{
    const int hd  = blockIdx.x;
    const int b   = blockIdx.y;
    const int dir = blockIdx.z;
    const int p   = threadIdx.x;
    const float Dh = D_param[hd];
    float h[64];
    #pragma unroll
    for (int n = 0; n < 64; n++) h[n] = 0.0f;

    __shared__ __align__(16) float Bs[64];
    __shared__ __align__(16) float Cs[64];

    for (int step = 0; step < SEQ; step++) {
        const int s = dir ? (SEQ - 1 - step) : step;
        const float* row = conv + ((size_t)(dir * BSZ + b) * SEQ + s) * CONV_DIM;
        __syncthreads();
        Bs[p] = row[D_INNER + p];
        Cs[p] = row[D_INNER + D_STATE + p];
        __syncthreads();
        const float xp = row[hd * HEADDIM + p];
        const int th = (b * SEQ + s) * NHEADS + hd;
        const float dt = dt_sp[th];
        const float da = dA_g[th];
        const float coeff = dt * xp;
        float acc = 0.0f;
        const float4* B4 = (const float4*)Bs;
        const float4* C4 = (const float4*)Cs;
        #pragma unroll
        for (int n4 = 0; n4 < 16; n4++) {
            float4 bb = B4[n4];
            float4 cc = C4[n4];
            h[4*n4+0] = da * h[4*n4+0] + coeff * bb.x;  acc += h[4*n4+0] * cc.x;
            h[4*n4+1] = da * h[4*n4+1] + coeff * bb.y;  acc += h[4*n4+1] * cc.y;
            h[4*n4+2] = da * h[4*n4+2] + coeff * bb.z;  acc += h[4*n4+2] * cc.z;
            h[4*n4+3] = da * h[4*n4+3] + coeff * bb.w;  acc += h[4*n4+3] * cc.w;
        }
        y_out[((size_t)(dir * BSZ + b) * SEQ + s) * D_INNER + hd * HEADDIM + p] = acc + Dh * xp;
    }
}

// ---------------- gate + RMSNorm -> bf16 hi/lo split ----------------
__global__ __launch_bounds__(256) void gate_bf_kernel(
    const float* __restrict__ y, const float* __restrict__ zx,
    const float* __restrict__ norm_w, __nv_bfloat16* __restrict__ hi,
    __nv_bfloat16* __restrict__ lo)
{
    __shared__ float sh[8];
    const int t = blockIdx.x;
    const int b = blockIdx.y;
    const size_t tok = (size_t)b * SEQ + t;
    const float* zrow = zx + tok * D_IN_PROJ;
    const float* yf = y + tok * D_INNER;
    const float* yb = y + ((size_t)BSZ * SEQ + tok) * D_INNER;

    float gf[6], gb[6];
    float sf = 0.0f, sb = 0.0f;
    #pragma unroll
    for (int i = 0; i < 6; i++) {
        int c = threadIdx.x + i * 256;
        float g = siluf_(zrow[c]);
        gf[i] = yf[c] * g;  sf += gf[i] * gf[i];
        gb[i] = yb[c] * g;  sb += gb[i] * gb[i];
    }
    sf = block_sum_256(sf, sh);
    sb = block_sum_256(sb, sh);
    const float scf = rsqrtf(sf * (1.0f / D_INNER) + EPS);
    const float scb = rsqrtf(sb * (1.0f / D_INNER) + EPS);
    #pragma unroll
    for (int i = 0; i < 6; i++) {
        int c = threadIdx.x + i * 256;
        float o = (gf[i] * scf + gb[i] * scb) * norm_w[c];
        __nv_bfloat16 h = __float2bfloat16(o);
        hi[tok * D_INNER + c] = h;
        lo[tok * D_INNER + c] = __float2bfloat16(o - __bfloat162float(h));
    }
}

// ---------------- launch ----------------
extern "C" void kernel_launch(void* const* d_in, const int* in_sizes, int n_in,
                              void* d_out, int out_size)
{
    const float* x          = (const float*)d_in[0];
    const float* in_proj_w  = (const float*)d_in[1];
    const float* conv_w     = (const float*)d_in[2];
    const float* conv_b     = (const float*)d_in[3];
    const float* dt_bias    = (const float*)d_in[4];
    const float* A_log      = (const float*)d_in[5];
    const float* D_param    = (const float*)d_in[6];
    const float* norm_w     = (const float*)d_in[7];
    const float* out_proj_w = (const float*)d_in[8];
    const float* ln1_w      = (const float*)d_in[9];
    const float* ln1_b      = (const float*)d_in[10];
    const float* ln2_w      = (const float*)d_in[11];
    const float* ln2_b      = (const float*)d_in[12];
    const float* ff_w1      = (const float*)d_in[13];
    const float* ff_b1      = (const float*)d_in[14];
    const float* ff_w2      = (const float*)d_in[15];
    const float* ff_b2      = (const float*)d_in[16];
    float* out = (float*)d_out;

    float *p_zx, *p_dt, *p_dA, *p_conv, *p_y, *p_mp;
    __nv_bfloat16 *p_w1h, *p_w1l, *p_w2h, *p_w2l, *p_w3h, *p_w3l, *p_w4h, *p_w4l;
    __nv_bfloat16 *p_a0h, *p_a0l, *p_a1h, *p_a1l;
    cudaGetSymbolAddress((void**)&p_zx,   g_zx);
    cudaGetSymbolAddress((void**)&p_dt,   g_dt);
    cudaGetSymbolAddress((void**)&p_dA,   g_dA);
    cudaGetSymbolAddress((void**)&p_conv, g_conv);
    cudaGetSymbolAddress((void**)&p_y,    g_y);
    cudaGetSymbolAddress((void**)&p_mp,   g_mp);
    cudaGetSymbolAddress((void**)&p_w1h,  g_w1h);  cudaGetSymbolAddress((void**)&p_w1l, g_w1l);
    cudaGetSymbolAddress((void**)&p_w2h,  g_w2h);  cudaGetSymbolAddress((void**)&p_w2l, g_w2l);
    cudaGetSymbolAddress((void**)&p_w3h,  g_w3h);  cudaGetSymbolAddress((void**)&p_w3l, g_w3l);
    cudaGetSymbolAddress((void**)&p_w4h,  g_w4h);  cudaGetSymbolAddress((void**)&p_w4l, g_w4l);
    cudaGetSymbolAddress((void**)&p_a0h,  g_a0h);  cudaGetSymbolAddress((void**)&p_a0l, g_a0l);
    cudaGetSymbolAddress((void**)&p_a1h,  g_a1h);  cudaGetSymbolAddress((void**)&p_a1l, g_a1l);

    // smem opt-in (host-side attribute set; idempotent)
    cudaFuncSetAttribute(mma_gemm_kernel<128,0>, cudaFuncAttributeMaxDynamicSharedMemorySize, 81920);
    cudaFuncSetAttribute(mma_gemm_kernel<128,1>, cudaFuncAttributeMaxDynamicSharedMemorySize, 81920);
    cudaFuncSetAttribute(mma_gemm_kernel<64,0>,  cudaFuncAttributeMaxDynamicSharedMemorySize, 61440);
    cudaFuncSetAttribute(mma_gemm_kernel<64,2>,  cudaFuncAttributeMaxDynamicSharedMemorySize, 61440);

    // 0) weight splits
    convw_kernel<<<(NPAD_INPROJ * D_MODEL / 4 + 255) / 256, 256>>>(in_proj_w,  p_w1h, p_w1l, D_IN_PROJ, NPAD_INPROJ, D_MODEL);
    convw_kernel<<<(D_MODEL * D_INNER  / 4 + 255) / 256, 256>>>(out_proj_w, p_w2h, p_w2l, D_MODEL, D_MODEL, D_INNER);
    convw_kernel<<<(D_FF * D_MODEL     / 4 + 255) / 256, 256>>>(ff_w1,      p_w3h, p_w3l, D_FF, D_FF, D_MODEL);
    convw_kernel<<<(D_MODEL * D_FF     / 4 + 255) / 256, 256>>>(ff_w2,      p_w4h, p_w4l, D_MODEL, D_MODEL, D_FF);

    // 1) LN1 -> a0 (hi/lo)
    ln_bf_kernel<<<NTOK, 256>>>(x, ln1_w, ln1_b, p_a0h, p_a0l);
    // 2) in_proj
    mma_gemm_kernel<128,0><<<dim3(NPAD_INPROJ/128, NTOK/128), 256, 81920>>>(
        p_a0h, p_a0l, p_w1h, p_w1l, nullptr, nullptr, p_zx, nullptr, nullptr,
        NTOK, D_IN_PROJ, D_MODEL);
    // 3) dt
    dt_kernel<<<(NTOK * NHEADS + 255) / 256, 256>>>(p_zx, dt_bias, A_log, p_dt, p_dA);
    // 4) conv + silu
    {
        long long total = 2LL * NTOK * CONV_DIM;
        conv_kernel<<<(unsigned)((total + 255) / 256), 256>>>(p_zx, conv_w, conv_b, p_conv);
    }
    // 5) scan
    scan_kernel<<<dim3(NHEADS, BSZ, 2), 64>>>(p_conv, p_dt, p_dA, D_param, p_y);
    // 6) gate + rmsnorm -> a0 (hi/lo)
    gate_bf_kernel<<<dim3(SEQ, BSZ), 256>>>(p_y, p_zx, norm_w, p_a0h, p_a0l);
    // 7) out_proj
    mma_gemm_kernel<64,0><<<dim3(D_MODEL/64, NTOK/128), 256, 61440>>>(
        p_a0h, p_a0l, p_w2h, p_w2l, nullptr, nullptr, p_mp, nullptr, nullptr,
        NTOK, D_MODEL, D_INNER);
    // 8) LN2 -> a0 (hi/lo)
    ln_bf_kernel<<<NTOK, 256>>>(p_mp, ln2_w, ln2_b, p_a0h, p_a0l);
    // 9) FFN1: gelu(m@W1+b1) -> a1 (hi/lo, fused split epilogue)
    mma_gemm_kernel<128,1><<<dim3(D_FF/128, NTOK/128), 256, 81920>>>(
        p_a0h, p_a0l, p_w3h, p_w3l, ff_b1, nullptr, nullptr, p_a1h, p_a1l,
        NTOK, D_FF, D_MODEL);
    // 10) FFN2 + bias + residual -> d_out
    mma_gemm_kernel<64,2><<<dim3(D_MODEL/64, NTOK/128), 256, 61440>>>(
        p_a1h, p_a1l, p_w4h, p_w4l, ff_b2, x, out, nullptr, nullptr,
        NTOK, D_MODEL, D_FF);
}

// round 10
// speedup vs baseline: 2.1652x; 1.1979x over previous
#include <cuda_runtime.h>
#include <cuda_bf16.h>
#include <math.h>
#include <stdint.h>

// ---------------- problem constants ----------------
#define D_MODEL   768
#define D_STATE   64
#define D_CONV    4
#define HEADDIM   64
#define D_INNER   1536
#define NHEADS    24
#define CONV_DIM  1664          // D_INNER + 2*D_STATE
#define D_IN_PROJ 3224          // 2*D_INNER + 2*D_STATE + NHEADS
#define BSZ       2
#define SEQ       512
#define NTOK      (BSZ*SEQ)     // 1024
#define EPS       1e-5f
#define D_FF      3072
#define NPAD_INPROJ 3328        // D_IN_PROJ padded to 128

// ---------------- scratch (device globals; no allocation allowed) ------------
__device__ float g_zx   [NTOK * D_IN_PROJ];
__device__ float g_dt   [NTOK * NHEADS];
__device__ float g_dA   [NTOK * NHEADS];
__device__ float g_conv [2 * NTOK * CONV_DIM];
__device__ float g_y    [2 * NTOK * D_INNER];
__device__ float g_mp   [NTOK * D_MODEL];

// bf16 split buffers
__device__ __nv_bfloat16 g_w1h[NPAD_INPROJ * D_MODEL], g_w1l[NPAD_INPROJ * D_MODEL];
__device__ __nv_bfloat16 g_w2h[D_MODEL * D_INNER],     g_w2l[D_MODEL * D_INNER];
__device__ __nv_bfloat16 g_w3h[D_FF * D_MODEL],        g_w3l[D_FF * D_MODEL];
__device__ __nv_bfloat16 g_w4h[D_MODEL * D_FF],        g_w4l[D_MODEL * D_FF];
__device__ __nv_bfloat16 g_a0h[NTOK * D_INNER],        g_a0l[NTOK * D_INNER];
__device__ __nv_bfloat16 g_a1h[NTOK * D_FF],           g_a1l[NTOK * D_FF];

// ---------------- small device helpers ----------------
__device__ __forceinline__ float sigmoidf_(float x) { return 1.0f / (1.0f + __expf(-x)); }
__device__ __forceinline__ float siluf_(float x)    { return x * sigmoidf_(x); }
__device__ __forceinline__ float softplusf_(float x){ return (x > 20.0f) ? x : log1pf(expf(x)); }
__device__ __forceinline__ float geluf_(float x)    { return 0.5f * x * (1.0f + erff(x * 0.70710678118654752f)); }

__device__ __forceinline__ float block_sum_256(float v, float* sh) {
    #pragma unroll
    for (int o = 16; o; o >>= 1) v += __shfl_xor_sync(0xffffffffu, v, o);
    if ((threadIdx.x & 31) == 0) sh[threadIdx.x >> 5] = v;
    __syncthreads();
    float s = (threadIdx.x < 8) ? sh[threadIdx.x] : 0.0f;
    if (threadIdx.x < 8) {
        #pragma unroll
        for (int o = 4; o; o >>= 1) s += __shfl_xor_sync(0xffu, s, o);
        if (threadIdx.x == 0) sh[0] = s;
    }
    __syncthreads();
    float r = sh[0];
    __syncthreads();
    return r;
}

__device__ __forceinline__ uint32_t smem_u32(const void* p) {
    uint32_t a;
    asm("{ .reg .u64 t; cvta.to.shared.u64 t, %1; cvt.u32.u64 %0, t; }" : "=r"(a) : "l"(p));
    return a;
}

__device__ __forceinline__ void cp16(uint32_t s, const void* g) {
    asm volatile("cp.async.cg.shared.global [%0], [%1], 16;" :: "r"(s), "l"(g));
}
__device__ __forceinline__ void cp_commit() {
    asm volatile("cp.async.commit_group;" ::: "memory");
}
template<int N>
__device__ __forceinline__ void cp_wait() {
    asm volatile("cp.async.wait_group %0;" :: "n"(N) : "memory");
}

#define LDMX4(R0,R1,R2,R3,ADDR) \
    asm volatile("ldmatrix.sync.aligned.m8n8.x4.shared.b16 {%0,%1,%2,%3}, [%4];" \
        : "=r"(R0),"=r"(R1),"=r"(R2),"=r"(R3) : "r"(ADDR))

#define MMA16816(D,A,B) \
    asm volatile("mma.sync.aligned.m16n8k16.row.col.f32.bf16.bf16.f32 " \
        "{%0,%1,%2,%3},{%4,%5,%6,%7},{%8,%9},{%0,%1,%2,%3};" \
        : "+f"((D)[0]),"+f"((D)[1]),"+f"((D)[2]),"+f"((D)[3]) \
        : "r"((A)[0]),"r"((A)[1]),"r"((A)[2]),"r"((A)[3]), "r"((B)[0]),"r"((B)[1]))

__device__ __forceinline__ uint32_t packbf(__nv_bfloat16 a, __nv_bfloat16 b) {
    return ((uint32_t)__bfloat16_as_ushort(b) << 16) | __bfloat16_as_ushort(a);
}

// =============================================================================
// Weight fp32 -> bf16 hi/lo split (with row padding to Npad)
// =============================================================================
__global__ __launch_bounds__(256) void convw_kernel(
    const float* __restrict__ W, __nv_bfloat16* __restrict__ hi,
    __nv_bfloat16* __restrict__ lo, int Ntrue, int Npad, int K)
{
    int i4 = blockIdx.x * 256 + threadIdx.x;
    int total = (Npad * K) >> 2;
    if (i4 >= total) return;
    size_t e = (size_t)i4 * 4;
    int n = (int)(e / (size_t)K);
    float4 v = make_float4(0.f, 0.f, 0.f, 0.f);
    if (n < Ntrue) v = *(const float4*)(W + e);
    __nv_bfloat16 h0 = __float2bfloat16(v.x), h1 = __float2bfloat16(v.y);
    __nv_bfloat16 h2 = __float2bfloat16(v.z), h3 = __float2bfloat16(v.w);
    __nv_bfloat16 l0 = __float2bfloat16(v.x - __bfloat162float(h0));
    __nv_bfloat16 l1 = __float2bfloat16(v.y - __bfloat162float(h1));
    __nv_bfloat16 l2 = __float2bfloat16(v.z - __bfloat162float(h2));
    __nv_bfloat16 l3 = __float2bfloat16(v.w - __bfloat162float(h3));
    *(uint2*)(hi + e) = make_uint2(packbf(h0,h1), packbf(h2,h3));
    *(uint2*)(lo + e) = make_uint2(packbf(l0,l1), packbf(l2,l3));
}

// =============================================================================
// mma.sync split-bf16 GEMM with cp.async 3-stage pipeline
// C[M,N] = A[M,K] @ W[N,K]^T ; BM=128, BN in {128,64}; 256 thr; KC=32
// smem rows: 64B data + 16B pad (pitch 80). All shapes tile-exact (no guards
// in copies; N-raggedness handled only in epilogue).
// EPI 0: C=acc   EPI 1: gelu(acc+bias)->Chi/Clo   EPI 2: acc+bias+resid
// =============================================================================
template<int BN, int EPI>
__global__ __launch_bounds__(256) void mma_gemm_kernel(
    const __nv_bfloat16* __restrict__ Ahi, const __nv_bfloat16* __restrict__ Alo,
    const __nv_bfloat16* __restrict__ Whi, const __nv_bfloat16* __restrict__ Wlo,
    const float* __restrict__ bias, const float* __restrict__ resid,
    float* __restrict__ C, __nv_bfloat16* __restrict__ Chi, __nv_bfloat16* __restrict__ Clo,
    int M, int N, int K)
{
    constexpr int NJ     = BN / 32;            // n8 tiles per warp
    constexpr int OFF_AL = 128 * 80;           // 10240
    constexpr int OFF_BH = 2 * 128 * 80;       // 20480
    constexpr int BBYTES = BN * 80;
    constexpr int OFF_BL = OFF_BH + BBYTES;
    constexpr int STAGE  = OFF_BH + 2 * BBYTES;

    extern __shared__ char sm[];
    const uint32_t sb = smem_u32(sm);

    const int tid  = threadIdx.x;
    const int wid  = tid >> 5, lane = tid & 31;
    const int m0   = blockIdx.y * 128, n0 = blockIdx.x * BN;
    const int warp_m = (wid >> 2) * 64;
    const int warp_n = (wid & 3) * (BN / 4);

    const int cr = tid >> 2, cq = tid & 3;     // copy row 0..63, col chunk 0..3

    const __nv_bfloat16* pAh = Ahi + (size_t)(m0 + cr) * K + cq * 8;
    const __nv_bfloat16* pAl = Alo + (size_t)(m0 + cr) * K + cq * 8;
    const __nv_bfloat16* pBh = Whi + (size_t)(n0 + cr) * K + cq * 8;
    const __nv_bfloat16* pBl = Wlo + (size_t)(n0 + cr) * K + cq * 8;
    const uint32_t so = (uint32_t)(cr * 80 + cq * 16);

    auto ISSUE = [&](int kc, int slot) {
        const uint32_t st = sb + slot * STAGE;
        const int ko = kc * 32;
        cp16(st + so,                    pAh + ko);
        cp16(st + so + 64 * 80,          pAh + ko + (size_t)64 * K);
        cp16(st + OFF_AL + so,           pAl + ko);
        cp16(st + OFF_AL + so + 64 * 80, pAl + ko + (size_t)64 * K);
        cp16(st + OFF_BH + so,           pBh + ko);
        cp16(st + OFF_BL + so,           pBl + ko);
        if (BN == 128) {
            cp16(st + OFF_BH + so + 64 * 80, pBh + ko + (size_t)64 * K);
            cp16(st + OFF_BL + so + 64 * 80, pBl + ko + (size_t)64 * K);
        }
    };

    float acc[4][NJ][4];
    #pragma unroll
    for (int mi = 0; mi < 4; mi++)
        #pragma unroll
        for (int nj = 0; nj < NJ; nj++)
            #pragma unroll
            for (int t = 0; t < 4; t++) acc[mi][nj][t] = 0.0f;

    const int r_a  = (lane & 7) + ((lane >> 3) & 1) * 8;
    const int ch_a = ((lane >> 4) & 1) * 8;
    const int rB   = lane & 7, jB = lane >> 3;
    const int n_b  = ((jB >> 1) << 3) + rB;
    const int kh_b = (jB & 1) << 3;

    auto COMPUTE = [&](int slot) {
        const uint32_t Abase = sb + slot * STAGE;
        #pragma unroll
        for (int kk = 0; kk < 2; kk++) {
            uint32_t ah[4][4], al[4][4], bh[NJ][2], bl[NJ][2];
            #pragma unroll
            for (int mi = 0; mi < 4; mi++) {
                const uint32_t ad = Abase + (warp_m + mi * 16 + r_a) * 80 + (kk * 16 + ch_a) * 2;
                LDMX4(ah[mi][0], ah[mi][1], ah[mi][2], ah[mi][3], ad);
                LDMX4(al[mi][0], al[mi][1], al[mi][2], al[mi][3], ad + OFF_AL);
            }
            #pragma unroll
            for (int g = 0; g < NJ / 2; g++) {
                const uint32_t bd = Abase + OFF_BH + (warp_n + g * 16 + n_b) * 80 + (kk * 16 + kh_b) * 2;
                LDMX4(bh[2*g][0], bh[2*g][1], bh[2*g+1][0], bh[2*g+1][1], bd);
                LDMX4(bl[2*g][0], bl[2*g][1], bl[2*g+1][0], bl[2*g+1][1], bd + BBYTES);
            }
            #pragma unroll
            for (int mi = 0; mi < 4; mi++)
                #pragma unroll
                for (int nj = 0; nj < NJ; nj++) {
                    MMA16816(acc[mi][nj], ah[mi], bh[nj]);
                    MMA16816(acc[mi][nj], ah[mi], bl[nj]);
                    MMA16816(acc[mi][nj], al[mi], bh[nj]);
                }
        }
    };

    const int NK = K >> 5;
    ISSUE(0, 0); cp_commit();
    ISSUE(1, 1); cp_commit();
    for (int kc = 0; kc < NK; kc++) {
        cp_wait<1>();
        __syncthreads();
        if (kc + 2 < NK) ISSUE(kc + 2, (kc + 2) % 3);
        cp_commit();
        COMPUTE(kc % 3);
    }
    cp_wait<0>();

    // ---------------- epilogue ----------------
    const int lr = lane >> 2, lc = (lane & 3) * 2;
    #pragma unroll
    for (int mi = 0; mi < 4; mi++) {
        #pragma unroll
        for (int nj = 0; nj < NJ; nj++) {
            const int col = n0 + warp_n + nj * 8 + lc;
            if (col >= N) continue;
            #pragma unroll
            for (int hf = 0; hf < 2; hf++) {
                const int row = m0 + warp_m + mi * 16 + lr + hf * 8;
                float d0 = acc[mi][nj][hf * 2 + 0];
                float d1 = acc[mi][nj][hf * 2 + 1];
                if (EPI == 0) {
                    *(float2*)(C + (size_t)row * N + col) = make_float2(d0, d1);
                } else if (EPI == 1) {
                    float g0 = geluf_(d0 + bias[col]);
                    float g1 = geluf_(d1 + bias[col + 1]);
                    __nv_bfloat16 h0 = __float2bfloat16(g0), h1 = __float2bfloat16(g1);
                    __nv_bfloat16 l0 = __float2bfloat16(g0 - __bfloat162float(h0));
                    __nv_bfloat16 l1 = __float2bfloat16(g1 - __bfloat162float(h1));
                    *(__nv_bfloat162*)(Chi + (size_t)row * N + col) = __halves2bfloat162(h0, h1);
                    *(__nv_bfloat162*)(Clo + (size_t)row * N + col) = __halves2bfloat162(l0, l1);
                } else {
                    const float* rr = resid + (size_t)row * N + col;
                    *(float2*)(C + (size_t)row * N + col) =
                        make_float2(d0 + bias[col] + rr[0], d1 + bias[col + 1] + rr[1]);
                }
            }
        }
    }
}

// ---------------- layernorm -> bf16 hi/lo split output ----------------
__global__ __launch_bounds__(256) void ln_bf_kernel(
    const float* __restrict__ x, const float* __restrict__ w,
    const float* __restrict__ b, __nv_bfloat16* __restrict__ hi,
    __nv_bfloat16* __restrict__ lo)
{
    __shared__ float sh[8];
    const int tok = blockIdx.x;
    const float* xi = x + (size_t)tok * D_MODEL;
    float v[3];
    #pragma unroll
    for (int i = 0; i < 3; i++) v[i] = xi[threadIdx.x + i * 256];
    float s = v[0] + v[1] + v[2];
    s = block_sum_256(s, sh);
    const float mu = s * (1.0f / D_MODEL);
    float c[3], sq = 0.0f;
    #pragma unroll
    for (int i = 0; i < 3; i++) { c[i] = v[i] - mu; sq += c[i] * c[i]; }
    sq = block_sum_256(sq, sh);
    const float rstd = rsqrtf(sq * (1.0f / D_MODEL) + EPS);
    #pragma unroll
    for (int i = 0; i < 3; i++) {
        int idx = threadIdx.x + i * 256;
        float o = c[i] * rstd * w[idx] + b[idx];
        __nv_bfloat16 h = __float2bfloat16(o);
        hi[(size_t)tok * D_MODEL + idx] = h;
        lo[(size_t)tok * D_MODEL + idx] = __float2bfloat16(o - __bfloat162float(h));
    }
}

// ---------------- dt preprocessing ----------------
__global__ __launch_bounds__(256) void dt_kernel(
    const float* __restrict__ zx, const float* __restrict__ dt_bias,
    const float* __restrict__ A_log, float* __restrict__ dt_sp, float* __restrict__ dA)
{
    int idx = blockIdx.x * 256 + threadIdx.x;
    if (idx >= NTOK * NHEADS) return;
    int h = idx % NHEADS;
    int tok = idx / NHEADS;
    float v = zx[(size_t)tok * D_IN_PROJ + 3200 + h];
    float sp = softplusf_(v + dt_bias[h]);
    dt_sp[idx] = sp;
    dA[idx] = __expf(-__expf(A_log[h]) * sp);
}

// ---------------- conv1d (+bias, silu), both directions ----------------
__global__ __launch_bounds__(256) void conv_kernel(
    const float* __restrict__ zx, const float* __restrict__ conv_w,
    const float* __restrict__ conv_b, float* __restrict__ out)
{
    long long idx = (long long)blockIdx.x * 256 + threadIdx.x;
    const long long total = 2LL * NTOK * CONV_DIM;
    if (idx >= total) return;
    int c = (int)(idx % CONV_DIM);
    long long r = idx / CONV_DIM;
    int t = (int)(r % SEQ);
    r /= SEQ;
    int b = (int)(r % BSZ);
    int dir = (int)(r / BSZ);
    const float4 w = *(const float4*)(conv_w + (size_t)c * 4);
    const float* base = zx + ((size_t)b * SEQ) * D_IN_PROJ + D_INNER + c;
    float acc = 0.0f;
    if (dir == 0) {
        if (t >= 3) acc += w.x * base[(size_t)(t - 3) * D_IN_PROJ];
        if (t >= 2) acc += w.y * base[(size_t)(t - 2) * D_IN_PROJ];
        if (t >= 1) acc += w.z * base[(size_t)(t - 1) * D_IN_PROJ];
        acc += w.w * base[(size_t)t * D_IN_PROJ];
    } else {
        if (t + 3 < SEQ) acc += w.x * base[(size_t)(t + 3) * D_IN_PROJ];
        if (t + 2 < SEQ) acc += w.y * base[(size_t)(t + 2) * D_IN_PROJ];
        if (t + 1 < SEQ) acc += w.z * base[(size_t)(t + 1) * D_IN_PROJ];
        acc += w.w * base[(size_t)t * D_IN_PROJ];
    }
    acc += conv_b[c];
    out[idx] = siluf_(acc);
}

// ---------------- SSM scan: 1 block / (head,batch,dir); 128 threads ----------
// p = tid>>1 (headdim lane), g = tid&1 (n-half). Pair (p,0)/(p,1) in same warp
// -> reduction via shfl_xor 1. Distance-1 register prefetch; double-buffered
// B/C staging with ONE barrier per step.
__global__ __launch_bounds__(128) void scan_kernel(
    const float* __restrict__ conv, const float* __restrict__ dt_sp,
    const float* __restrict__ dA_g, const float* __restrict__ D_param,
    float* __restrict__ y_out)
{
    const int hd  = blockIdx.x;
    const int b   = blockIdx.y;
    const int dir = blockIdx.z;
    const int tid = threadIdx.x;
    const int p   = tid >> 1;
    const int g   = tid & 1;
    const float Dh = D_param[hd];

    float h[32];
    #pragma unroll
    for (int n = 0; n < 32; n++) h[n] = 0.0f;

    __shared__ __align__(16) float Bs[2][64];
    __shared__ __align__(16) float Cs[2][64];

    const size_t seq_base = (size_t)(dir * BSZ + b) * SEQ;

    // prefetch step 0
    float pBC, pX, pDT, pDA;
    {
        const int s0 = dir ? (SEQ - 1) : 0;
        const float* row = conv + (seq_base + s0) * CONV_DIM;
        pBC = row[D_INNER + g * D_STATE + p];
        pX  = row[hd * HEADDIM + p];
        const int th = (b * SEQ + s0) * NHEADS + hd;
        pDT = dt_sp[th];
        pDA = dA_g[th];
    }

    for (int step = 0; step < SEQ; step++) {
        const int buf = step & 1;
        const int s = dir ? (SEQ - 1 - step) : step;

        if (g == 0) Bs[buf][p] = pBC;
        else        Cs[buf][p] = pBC;
        const float xv  = pX;
        const float dtv = pDT;
        const float dav = pDA;
        __syncthreads();

        // prefetch step+1 (clamped at the end)
        {
            const int sn = (step + 1 < SEQ) ? step + 1 : step;
            const int ss = dir ? (SEQ - 1 - sn) : sn;
            const float* row = conv + (seq_base + ss) * CONV_DIM;
            pBC = row[D_INNER + g * D_STATE + p];
            pX  = row[hd * HEADDIM + p];
            const int th = (b * SEQ + ss) * NHEADS + hd;
            pDT = dt_sp[th];
            pDA = dA_g[th];
        }

        const float coeff = dtv * xv;
        const float4* B4 = (const float4*)(Bs[buf] + g * 32);
        const float4* C4 = (const float4*)(Cs[buf] + g * 32);
        float a0 = 0.f, a1 = 0.f, a2 = 0.f, a3 = 0.f;
        #pragma unroll
        for (int q = 0; q < 8; q++) {
            float4 bb = B4[q];
            float4 cc = C4[q];
            h[4*q+0] = fmaf(dav, h[4*q+0], coeff * bb.x);  a0 = fmaf(h[4*q+0], cc.x, a0);
            h[4*q+1] = fmaf(dav, h[4*q+1], coeff * bb.y);  a1 = fmaf(h[4*q+1], cc.y, a1);
            h[4*q+2] = fmaf(dav, h[4*q+2], coeff * bb.z);  a2 = fmaf(h[4*q+2], cc.z, a2);
            h[4*q+3] = fmaf(dav, h[4*q+3], coeff * bb.w);  a3 = fmaf(h[4*q+3], cc.w, a3);
        }
        float acc = (a0 + a1) + (a2 + a3);
        acc += __shfl_xor_sync(0xffffffffu, acc, 1);
        if (!g) {
            y_out[(seq_base + s) * D_INNER + hd * HEADDIM + p] = acc + Dh * xv;
        }
    }
}

// ---------------- gate + RMSNorm -> bf16 hi/lo split ----------------
__global__ __launch_bounds__(256) void gate_bf_kernel(
    const float* __restrict__ y, const float* __restrict__ zx,
    const float* __restrict__ norm_w, __nv_bfloat16* __restrict__ hi,
    __nv_bfloat16* __restrict__ lo)
{
    __shared__ float sh[8];
    const int t = blockIdx.x;
    const int b = blockIdx.y;
    const size_t tok = (size_t)b * SEQ + t;
    const float* zrow = zx + tok * D_IN_PROJ;
    const float* yf = y + tok * D_INNER;
    const float* yb = y + ((size_t)BSZ * SEQ + tok) * D_INNER;

    float gf[6], gb[6];
    float sf = 0.0f, sb = 0.0f;
    #pragma unroll
    for (int i = 0; i < 6; i++) {
        int c = threadIdx.x + i * 256;
        float g = siluf_(zrow[c]);
        gf[i] = yf[c] * g;  sf += gf[i] * gf[i];
        gb[i] = yb[c] * g;  sb += gb[i] * gb[i];
    }
    sf = block_sum_256(sf, sh);
    sb = block_sum_256(sb, sh);
    const float scf = rsqrtf(sf * (1.0f / D_INNER) + EPS);
    const float scb = rsqrtf(sb * (1.0f / D_INNER) + EPS);
    #pragma unroll
    for (int i = 0; i < 6; i++) {
        int c = threadIdx.x + i * 256;
        float o = (gf[i] * scf + gb[i] * scb) * norm_w[c];
        __nv_bfloat16 h = __float2bfloat16(o);
        hi[tok * D_INNER + c] = h;
        lo[tok * D_INNER + c] = __float2bfloat16(o - __bfloat162float(h));
    }
}

// ---------------- launch ----------------
extern "C" void kernel_launch(void* const* d_in, const int* in_sizes, int n_in,
                              void* d_out, int out_size)
{
    const float* x          = (const float*)d_in[0];
    const float* in_proj_w  = (const float*)d_in[1];
    const float* conv_w     = (const float*)d_in[2];
    const float* conv_b     = (const float*)d_in[3];
    const float* dt_bias    = (const float*)d_in[4];
    const float* A_log      = (const float*)d_in[5];
    const float* D_param    = (const float*)d_in[6];
    const float* norm_w     = (const float*)d_in[7];
    const float* out_proj_w = (const float*)d_in[8];
    const float* ln1_w      = (const float*)d_in[9];
    const float* ln1_b      = (const float*)d_in[10];
    const float* ln2_w      = (const float*)d_in[11];
    const float* ln2_b      = (const float*)d_in[12];
    const float* ff_w1      = (const float*)d_in[13];
    const float* ff_b1      = (const float*)d_in[14];
    const float* ff_w2      = (const float*)d_in[15];
    const float* ff_b2      = (const float*)d_in[16];
    float* out = (float*)d_out;

    float *p_zx, *p_dt, *p_dA, *p_conv, *p_y, *p_mp;
    __nv_bfloat16 *p_w1h, *p_w1l, *p_w2h, *p_w2l, *p_w3h, *p_w3l, *p_w4h, *p_w4l;
    __nv_bfloat16 *p_a0h, *p_a0l, *p_a1h, *p_a1l;
    cudaGetSymbolAddress((void**)&p_zx,   g_zx);
    cudaGetSymbolAddress((void**)&p_dt,   g_dt);
    cudaGetSymbolAddress((void**)&p_dA,   g_dA);
    cudaGetSymbolAddress((void**)&p_conv, g_conv);
    cudaGetSymbolAddress((void**)&p_y,    g_y);
    cudaGetSymbolAddress((void**)&p_mp,   g_mp);
    cudaGetSymbolAddress((void**)&p_w1h,  g_w1h);  cudaGetSymbolAddress((void**)&p_w1l, g_w1l);
    cudaGetSymbolAddress((void**)&p_w2h,  g_w2h);  cudaGetSymbolAddress((void**)&p_w2l, g_w2l);
    cudaGetSymbolAddress((void**)&p_w3h,  g_w3h);  cudaGetSymbolAddress((void**)&p_w3l, g_w3l);
    cudaGetSymbolAddress((void**)&p_w4h,  g_w4h);  cudaGetSymbolAddress((void**)&p_w4l, g_w4l);
    cudaGetSymbolAddress((void**)&p_a0h,  g_a0h);  cudaGetSymbolAddress((void**)&p_a0l, g_a0l);
    cudaGetSymbolAddress((void**)&p_a1h,  g_a1h);  cudaGetSymbolAddress((void**)&p_a1l, g_a1l);

    // smem opt-in (host-side attribute set; idempotent)
    cudaFuncSetAttribute(mma_gemm_kernel<128,0>, cudaFuncAttributeMaxDynamicSharedMemorySize, 122880);
    cudaFuncSetAttribute(mma_gemm_kernel<128,1>, cudaFuncAttributeMaxDynamicSharedMemorySize, 122880);
    cudaFuncSetAttribute(mma_gemm_kernel<64,0>,  cudaFuncAttributeMaxDynamicSharedMemorySize, 92160);
    cudaFuncSetAttribute(mma_gemm_kernel<64,2>,  cudaFuncAttributeMaxDynamicSharedMemorySize, 92160);

    // 0) weight splits
    convw_kernel<<<(NPAD_INPROJ * D_MODEL / 4 + 255) / 256, 256>>>(in_proj_w,  p_w1h, p_w1l, D_IN_PROJ, NPAD_INPROJ, D_MODEL);
    convw_kernel<<<(D_MODEL * D_INNER  / 4 + 255) / 256, 256>>>(out_proj_w, p_w2h, p_w2l, D_MODEL, D_MODEL, D_INNER);
    convw_kernel<<<(D_FF * D_MODEL     / 4 + 255) / 256, 256>>>(ff_w1,      p_w3h, p_w3l, D_FF, D_FF, D_MODEL);
    convw_kernel<<<(D_MODEL * D_FF     / 4 + 255) / 256, 256>>>(ff_w2,      p_w4h, p_w4l, D_MODEL, D_MODEL, D_FF);

    // 1) LN1 -> a0 (hi/lo)
    ln_bf_kernel<<<NTOK, 256>>>(x, ln1_w, ln1_b, p_a0h, p_a0l);
    // 2) in_proj
    mma_gemm_kernel<128,0><<<dim3(NPAD_INPROJ/128, NTOK/128), 256, 122880>>>(
        p_a0h, p_a0l, p_w1h, p_w1l, nullptr, nullptr, p_zx, nullptr, nullptr,
        NTOK, D_IN_PROJ, D_MODEL);
    // 3) dt
    dt_kernel<<<(NTOK * NHEADS + 255) / 256, 256>>>(p_zx, dt_bias, A_log, p_dt, p_dA);
    // 4) conv + silu
    {
        long long total = 2LL * NTOK * CONV_DIM;
        conv_kernel<<<(unsigned)((total + 255) / 256), 256>>>(p_zx, conv_w, conv_b, p_conv);
    }
    // 5) scan
    scan_kernel<<<dim3(NHEADS, BSZ, 2), 128>>>(p_conv, p_dt, p_dA, D_param, p_y);
    // 6) gate + rmsnorm -> a0 (hi/lo)
    gate_bf_kernel<<<dim3(SEQ, BSZ), 256>>>(p_y, p_zx, norm_w, p_a0h, p_a0l);
    // 7) out_proj
    mma_gemm_kernel<64,0><<<dim3(D_MODEL/64, NTOK/128), 256, 92160>>>(
        p_a0h, p_a0l, p_w2h, p_w2l, nullptr, nullptr, p_mp, nullptr, nullptr,
        NTOK, D_MODEL, D_INNER);
    // 8) LN2 -> a0 (hi/lo)
    ln_bf_kernel<<<NTOK, 256>>>(p_mp, ln2_w, ln2_b, p_a0h, p_a0l);
    // 9) FFN1: gelu(m@W1+b1) -> a1 (hi/lo, fused split epilogue)
    mma_gemm_kernel<128,1><<<dim3(D_FF/128, NTOK/128), 256, 122880>>>(
        p_a0h, p_a0l, p_w3h, p_w3l, ff_b1, nullptr, nullptr, p_a1h, p_a1l,
        NTOK, D_FF, D_MODEL);
    // 10) FFN2 + bias + residual -> d_out
    mma_gemm_kernel<64,2><<<dim3(D_MODEL/64, NTOK/128), 256, 92160>>>(
        p_a1h, p_a1l, p_w4h, p_w4l, ff_b2, x, out, nullptr, nullptr,
        NTOK, D_MODEL, D_FF);
}

// round 11
// speedup vs baseline: 2.2881x; 1.0567x over previous
#include <cuda_runtime.h>
#include <cuda_bf16.h>
#include <math.h>
#include <stdint.h>

// ---------------- problem constants ----------------
#define D_MODEL   768
#define D_STATE   64
#define D_CONV    4
#define HEADDIM   64
#define D_INNER   1536
#define NHEADS    24
#define CONV_DIM  1664          // D_INNER + 2*D_STATE
#define D_IN_PROJ 3224          // 2*D_INNER + 2*D_STATE + NHEADS
#define BSZ       2
#define SEQ       512
#define NTOK      (BSZ*SEQ)     // 1024
#define EPS       1e-5f
#define D_FF      3072
#define NPAD_INPROJ 3328        // D_IN_PROJ padded to 128

// ---------------- scratch (device globals; no allocation allowed) ------------
__device__ float g_zx   [NTOK * D_IN_PROJ];
__device__ float g_dt   [NTOK * NHEADS];
__device__ float g_dA   [NTOK * NHEADS];
__device__ float g_conv [2 * NTOK * CONV_DIM];
__device__ float g_y    [2 * NTOK * D_INNER];
__device__ float g_mp   [NTOK * D_MODEL];

// bf16 split buffers
__device__ __nv_bfloat16 g_w1h[NPAD_INPROJ * D_MODEL], g_w1l[NPAD_INPROJ * D_MODEL];
__device__ __nv_bfloat16 g_w2h[D_MODEL * D_INNER],     g_w2l[D_MODEL * D_INNER];
__device__ __nv_bfloat16 g_w3h[D_FF * D_MODEL],        g_w3l[D_FF * D_MODEL];
__device__ __nv_bfloat16 g_w4h[D_MODEL * D_FF],        g_w4l[D_MODEL * D_FF];
__device__ __nv_bfloat16 g_a0h[NTOK * D_INNER],        g_a0l[NTOK * D_INNER];
__device__ __nv_bfloat16 g_a1h[NTOK * D_FF],           g_a1l[NTOK * D_FF];

// ---------------- small device helpers ----------------
__device__ __forceinline__ float sigmoidf_(float x) { return 1.0f / (1.0f + __expf(-x)); }
__device__ __forceinline__ float siluf_(float x)    { return x * sigmoidf_(x); }
__device__ __forceinline__ float softplusf_(float x){ return (x > 20.0f) ? x : log1pf(expf(x)); }
__device__ __forceinline__ float geluf_(float x)    { return 0.5f * x * (1.0f + erff(x * 0.70710678118654752f)); }

__device__ __forceinline__ float block_sum_256(float v, float* sh) {
    #pragma unroll
    for (int o = 16; o; o >>= 1) v += __shfl_xor_sync(0xffffffffu, v, o);
    if ((threadIdx.x & 31) == 0) sh[threadIdx.x >> 5] = v;
    __syncthreads();
    float s = (threadIdx.x < 8) ? sh[threadIdx.x] : 0.0f;
    if (threadIdx.x < 8) {
        #pragma unroll
        for (int o = 4; o; o >>= 1) s += __shfl_xor_sync(0xffu, s, o);
        if (threadIdx.x == 0) sh[0] = s;
    }
    __syncthreads();
    float r = sh[0];
    __syncthreads();
    return r;
}

__device__ __forceinline__ uint32_t smem_u32(const void* p) {
    uint32_t a;
    asm("{ .reg .u64 t; cvta.to.shared.u64 t, %1; cvt.u32.u64 %0, t; }" : "=r"(a) : "l"(p));
    return a;
}

__device__ __forceinline__ void cp16(uint32_t s, const void* g) {
    asm volatile("cp.async.cg.shared.global [%0], [%1], 16;" :: "r"(s), "l"(g));
}
__device__ __forceinline__ void cp_commit() {
    asm volatile("cp.async.commit_group;" ::: "memory");
}
template<int N>
__device__ __forceinline__ void cp_wait() {
    asm volatile("cp.async.wait_group %0;" :: "n"(N) : "memory");
}

#define LDMX4(R0,R1,R2,R3,ADDR) \
    asm volatile("ldmatrix.sync.aligned.m8n8.x4.shared.b16 {%0,%1,%2,%3}, [%4];" \
        : "=r"(R0),"=r"(R1),"=r"(R2),"=r"(R3) : "r"(ADDR))

#define MMA16816(D,A,B) \
    asm volatile("mma.sync.aligned.m16n8k16.row.col.f32.bf16.bf16.f32 " \
        "{%0,%1,%2,%3},{%4,%5,%6,%7},{%8,%9},{%0,%1,%2,%3};" \
        : "+f"((D)[0]),"+f"((D)[1]),"+f"((D)[2]),"+f"((D)[3]) \
        : "r"((A)[0]),"r"((A)[1]),"r"((A)[2]),"r"((A)[3]), "r"((B)[0]),"r"((B)[1]))

__device__ __forceinline__ uint32_t packbf(__nv_bfloat16 a, __nv_bfloat16 b) {
    return ((uint32_t)__bfloat16_as_ushort(b) << 16) | __bfloat16_as_ushort(a);
}

// =============================================================================
// Fused weight fp32 -> bf16 hi/lo splits (4 matrices, 1 launch)
// =============================================================================
#define CW_S1 (NPAD_INPROJ * D_MODEL / 4)
#define CW_S2 (D_MODEL * D_INNER / 4)
#define CW_S3 (D_FF * D_MODEL / 4)
#define CW_S4 (D_MODEL * D_FF / 4)
#define CW_TOTAL (CW_S1 + CW_S2 + CW_S3 + CW_S4)

__global__ __launch_bounds__(256) void convw4_kernel(
    const float* __restrict__ W1, const float* __restrict__ W2,
    const float* __restrict__ W3, const float* __restrict__ W4,
    __nv_bfloat16* __restrict__ h1, __nv_bfloat16* __restrict__ l1,
    __nv_bfloat16* __restrict__ h2, __nv_bfloat16* __restrict__ l2,
    __nv_bfloat16* __restrict__ h3, __nv_bfloat16* __restrict__ l3,
    __nv_bfloat16* __restrict__ h4, __nv_bfloat16* __restrict__ l4)
{
    int i4 = blockIdx.x * 256 + threadIdx.x;
    const float* W; __nv_bfloat16 *hi, *lo; int Ntrue, K; size_t loc;
    if (i4 < CW_S1)                { W=W1; hi=h1; lo=l1; Ntrue=D_IN_PROJ; K=D_MODEL; loc=i4; }
    else if (i4 < CW_S1+CW_S2)     { W=W2; hi=h2; lo=l2; Ntrue=D_MODEL;   K=D_INNER; loc=i4-CW_S1; }
    else if (i4 < CW_S1+CW_S2+CW_S3){W=W3; hi=h3; lo=l3; Ntrue=D_FF;      K=D_MODEL; loc=i4-CW_S1-CW_S2; }
    else if (i4 < CW_TOTAL)        { W=W4; hi=h4; lo=l4; Ntrue=D_MODEL;   K=D_FF;    loc=i4-CW_S1-CW_S2-CW_S3; }
    else return;
    size_t e = loc * 4;
    int n = (int)(e / (size_t)K);
    float4 v = make_float4(0.f, 0.f, 0.f, 0.f);
    if (n < Ntrue) v = *(const float4*)(W + e);
    __nv_bfloat16 h0 = __float2bfloat16(v.x), h1_ = __float2bfloat16(v.y);
    __nv_bfloat16 h2_ = __float2bfloat16(v.z), h3_ = __float2bfloat16(v.w);
    __nv_bfloat16 l0 = __float2bfloat16(v.x - __bfloat162float(h0));
    __nv_bfloat16 l1_ = __float2bfloat16(v.y - __bfloat162float(h1_));
    __nv_bfloat16 l2_ = __float2bfloat16(v.z - __bfloat162float(h2_));
    __nv_bfloat16 l3_ = __float2bfloat16(v.w - __bfloat162float(h3_));
    *(uint2*)(hi + e) = make_uint2(packbf(h0,h1_), packbf(h2_,h3_));
    *(uint2*)(lo + e) = make_uint2(packbf(l0,l1_), packbf(l2_,l3_));
}

// =============================================================================
// mma.sync split-bf16 GEMM, BM=128 x BN=128, 256 thr, 2-stage cp.async,
// 2 CTAs/SM. EPI 0: C=acc fp32   EPI 1: gelu(acc+bias)->Chi/Clo bf16 split
// =============================================================================
template<int EPI>
__global__ __launch_bounds__(256, 2) void mma_gemm_kernel(
    const __nv_bfloat16* __restrict__ Ahi, const __nv_bfloat16* __restrict__ Alo,
    const __nv_bfloat16* __restrict__ Whi, const __nv_bfloat16* __restrict__ Wlo,
    const float* __restrict__ bias,
    float* __restrict__ C, __nv_bfloat16* __restrict__ Chi, __nv_bfloat16* __restrict__ Clo,
    int M, int N, int K)
{
    constexpr int NJ     = 4;
    constexpr int OFF_AL = 128 * 80;           // 10240
    constexpr int OFF_BH = 2 * 128 * 80;       // 20480
    constexpr int BBYTES = 128 * 80;
    constexpr int OFF_BL = OFF_BH + BBYTES;
    constexpr int STAGE  = OFF_BH + 2 * BBYTES;   // 40960

    extern __shared__ char sm[];
    const uint32_t sb = smem_u32(sm);

    const int tid  = threadIdx.x;
    const int wid  = tid >> 5, lane = tid & 31;
    const int m0   = blockIdx.y * 128, n0 = blockIdx.x * 128;
    const int warp_m = (wid >> 2) * 64;
    const int warp_n = (wid & 3) * 32;

    const int cr = tid >> 2, cq = tid & 3;

    const __nv_bfloat16* pAh = Ahi + (size_t)(m0 + cr) * K + cq * 8;
    const __nv_bfloat16* pAl = Alo + (size_t)(m0 + cr) * K + cq * 8;
    const __nv_bfloat16* pBh = Whi + (size_t)(n0 + cr) * K + cq * 8;
    const __nv_bfloat16* pBl = Wlo + (size_t)(n0 + cr) * K + cq * 8;
    const uint32_t so = (uint32_t)(cr * 80 + cq * 16);

    auto ISSUE = [&](int kc, int slot) {
        const uint32_t st = sb + slot * STAGE;
        const int ko = kc * 32;
        cp16(st + so,                    pAh + ko);
        cp16(st + so + 64 * 80,          pAh + ko + (size_t)64 * K);
        cp16(st + OFF_AL + so,           pAl + ko);
        cp16(st + OFF_AL + so + 64 * 80, pAl + ko + (size_t)64 * K);
        cp16(st + OFF_BH + so,           pBh + ko);
        cp16(st + OFF_BH + so + 64 * 80, pBh + ko + (size_t)64 * K);
        cp16(st + OFF_BL + so,           pBl + ko);
        cp16(st + OFF_BL + so + 64 * 80, pBl + ko + (size_t)64 * K);
    };

    float acc[4][NJ][4];
    #pragma unroll
    for (int mi = 0; mi < 4; mi++)
        #pragma unroll
        for (int nj = 0; nj < NJ; nj++)
            #pragma unroll
            for (int t = 0; t < 4; t++) acc[mi][nj][t] = 0.0f;

    const int r_a  = (lane & 7) + ((lane >> 3) & 1) * 8;
    const int ch_a = ((lane >> 4) & 1) * 8;
    const int rB   = lane & 7, jB = lane >> 3;
    const int n_b  = ((jB >> 1) << 3) + rB;
    const int kh_b = (jB & 1) << 3;

    auto COMPUTE = [&](int slot) {
        const uint32_t Abase = sb + slot * STAGE;
        #pragma unroll
        for (int kk = 0; kk < 2; kk++) {
            uint32_t bh[NJ][2], bl[NJ][2];
            #pragma unroll
            for (int g = 0; g < NJ / 2; g++) {
                const uint32_t bd = Abase + OFF_BH + (warp_n + g * 16 + n_b) * 80 + (kk * 16 + kh_b) * 2;
                LDMX4(bh[2*g][0], bh[2*g][1], bh[2*g+1][0], bh[2*g+1][1], bd);
                LDMX4(bl[2*g][0], bl[2*g][1], bl[2*g+1][0], bl[2*g+1][1], bd + BBYTES);
            }
            #pragma unroll
            for (int mi = 0; mi < 4; mi++) {
                uint32_t ah[4], al[4];
                const uint32_t ad = Abase + (warp_m + mi * 16 + r_a) * 80 + (kk * 16 + ch_a) * 2;
                LDMX4(ah[0], ah[1], ah[2], ah[3], ad);
                LDMX4(al[0], al[1], al[2], al[3], ad + OFF_AL);
                #pragma unroll
                for (int nj = 0; nj < NJ; nj++) {
                    MMA16816(acc[mi][nj], ah, bh[nj]);
                    MMA16816(acc[mi][nj], ah, bl[nj]);
                    MMA16816(acc[mi][nj], al, bh[nj]);
                }
            }
        }
    };

    const int NK = K >> 5;
    ISSUE(0, 0); cp_commit();
    ISSUE(1, 1); cp_commit();
    for (int kc = 0; kc < NK; kc++) {
        cp_wait<1>();
        __syncthreads();
        COMPUTE(kc & 1);
        __syncthreads();
        if (kc + 2 < NK) ISSUE(kc + 2, kc & 1);
        cp_commit();
    }
    cp_wait<0>();

    // ---------------- epilogue ----------------
    const int lr = lane >> 2, lc = (lane & 3) * 2;
    #pragma unroll
    for (int mi = 0; mi < 4; mi++) {
        #pragma unroll
        for (int nj = 0; nj < NJ; nj++) {
            const int col = n0 + warp_n + nj * 8 + lc;
            if (col >= N) continue;
            #pragma unroll
            for (int hf = 0; hf < 2; hf++) {
                const int row = m0 + warp_m + mi * 16 + lr + hf * 8;
                float d0 = acc[mi][nj][hf * 2 + 0];
                float d1 = acc[mi][nj][hf * 2 + 1];
                if (EPI == 0) {
                    *(float2*)(C + (size_t)row * N + col) = make_float2(d0, d1);
                } else {
                    float g0 = geluf_(d0 + bias[col]);
                    float g1 = geluf_(d1 + bias[col + 1]);
                    __nv_bfloat16 h0 = __float2bfloat16(g0), h1 = __float2bfloat16(g1);
                    __nv_bfloat16 l0 = __float2bfloat16(g0 - __bfloat162float(h0));
                    __nv_bfloat16 l1 = __float2bfloat16(g1 - __bfloat162float(h1));
                    *(__nv_bfloat162*)(Chi + (size_t)row * N + col) = __halves2bfloat162(h0, h1);
                    *(__nv_bfloat162*)(Clo + (size_t)row * N + col) = __halves2bfloat162(l0, l1);
                }
            }
        }
    }
}

// =============================================================================
// mma.sync split-bf16 GEMM, BM=64 x BN=64, 128 thr, 3-stage cp.async,
// 3 CTAs/SM. EPI 0: C=acc fp32   EPI 2: acc + bias + resid
// =============================================================================
template<int EPI>
__global__ __launch_bounds__(128) void mma_gemm64_kernel(
    const __nv_bfloat16* __restrict__ Ahi, const __nv_bfloat16* __restrict__ Alo,
    const __nv_bfloat16* __restrict__ Whi, const __nv_bfloat16* __restrict__ Wlo,
    const float* __restrict__ bias, const float* __restrict__ resid,
    float* __restrict__ C, int M, int N, int K)
{
    constexpr int NJ     = 4;
    constexpr int OFF_AL = 64 * 80;            // 5120
    constexpr int OFF_BH = 2 * 64 * 80;        // 10240
    constexpr int BBYTES = 64 * 80;
    constexpr int OFF_BL = OFF_BH + BBYTES;    // 15360
    constexpr int STAGE  = OFF_BH + 2 * BBYTES;// 20480

    extern __shared__ char sm[];
    const uint32_t sb = smem_u32(sm);

    const int tid  = threadIdx.x;
    const int wid  = tid >> 5, lane = tid & 31;
    const int m0   = blockIdx.y * 64, n0 = blockIdx.x * 64;
    const int warp_m = (wid & 1) * 32;
    const int warp_n = (wid >> 1) * 32;

    const int cr = tid >> 2, cq = tid & 3;     // rows 0..31, col chunk 0..3

    const __nv_bfloat16* pAh = Ahi + (size_t)(m0 + cr) * K + cq * 8;
    const __nv_bfloat16* pAl = Alo + (size_t)(m0 + cr) * K + cq * 8;
    const __nv_bfloat16* pBh = Whi + (size_t)(n0 + cr) * K + cq * 8;
    const __nv_bfloat16* pBl = Wlo + (size_t)(n0 + cr) * K + cq * 8;
    const uint32_t so = (uint32_t)(cr * 80 + cq * 16);

    auto ISSUE = [&](int kc, int slot) {
        const uint32_t st = sb + slot * STAGE;
        const int ko = kc * 32;
        cp16(st + so,                    pAh + ko);
        cp16(st + so + 32 * 80,          pAh + ko + (size_t)32 * K);
        cp16(st + OFF_AL + so,           pAl + ko);
        cp16(st + OFF_AL + so + 32 * 80, pAl + ko + (size_t)32 * K);
        cp16(st + OFF_BH + so,           pBh + ko);
        cp16(st + OFF_BH + so + 32 * 80, pBh + ko + (size_t)32 * K);
        cp16(st + OFF_BL + so,           pBl + ko);
        cp16(st + OFF_BL + so + 32 * 80, pBl + ko + (size_t)32 * K);
    };

    float acc[2][NJ][4];
    #pragma unroll
    for (int mi = 0; mi < 2; mi++)
        #pragma unroll
        for (int nj = 0; nj < NJ; nj++)
            #pragma unroll
            for (int t = 0; t < 4; t++) acc[mi][nj][t] = 0.0f;

    const int r_a  = (lane & 7) + ((lane >> 3) & 1) * 8;
    const int ch_a = ((lane >> 4) & 1) * 8;
    const int rB   = lane & 7, jB = lane >> 3;
    const int n_b  = ((jB >> 1) << 3) + rB;
    const int kh_b = (jB & 1) << 3;

    auto COMPUTE = [&](int slot) {
        const uint32_t Abase = sb + slot * STAGE;
        #pragma unroll
        for (int kk = 0; kk < 2; kk++) {
            uint32_t bh[NJ][2], bl[NJ][2];
            #pragma unroll
            for (int g = 0; g < NJ / 2; g++) {
                const uint32_t bd = Abase + OFF_BH + (warp_n + g * 16 + n_b) * 80 + (kk * 16 + kh_b) * 2;
                LDMX4(bh[2*g][0], bh[2*g][1], bh[2*g+1][0], bh[2*g+1][1], bd);
                LDMX4(bl[2*g][0], bl[2*g][1], bl[2*g+1][0], bl[2*g+1][1], bd + BBYTES);
            }
            #pragma unroll
            for (int mi = 0; mi < 2; mi++) {
                uint32_t ah[4], al[4];
                const uint32_t ad = Abase + (warp_m + mi * 16 + r_a) * 80 + (kk * 16 + ch_a) * 2;
                LDMX4(ah[0], ah[1], ah[2], ah[3], ad);
                LDMX4(al[0], al[1], al[2], al[3], ad + OFF_AL);
                #pragma unroll
                for (int nj = 0; nj < NJ; nj++) {
                    MMA16816(acc[mi][nj], ah, bh[nj]);
                    MMA16816(acc[mi][nj], ah, bl[nj]);
                    MMA16816(acc[mi][nj], al, bh[nj]);
                }
            }
        }
    };

    const int NK = K >> 5;
    ISSUE(0, 0); cp_commit();
    ISSUE(1, 1); cp_commit();
    for (int kc = 0; kc < NK; kc++) {
        cp_wait<1>();
        __syncthreads();
        if (kc + 2 < NK) ISSUE(kc + 2, (kc + 2) % 3);
        cp_commit();
        COMPUTE(kc % 3);
    }
    cp_wait<0>();

    // ---------------- epilogue ----------------
    const int lr = lane >> 2, lc = (lane & 3) * 2;
    #pragma unroll
    for (int mi = 0; mi < 2; mi++) {
        #pragma unroll
        for (int nj = 0; nj < NJ; nj++) {
            const int col = n0 + warp_n + nj * 8 + lc;
            if (col >= N) continue;
            #pragma unroll
            for (int hf = 0; hf < 2; hf++) {
                const int row = m0 + warp_m + mi * 16 + lr + hf * 8;
                float d0 = acc[mi][nj][hf * 2 + 0];
                float d1 = acc[mi][nj][hf * 2 + 1];
                if (EPI == 0) {
                    *(float2*)(C + (size_t)row * N + col) = make_float2(d0, d1);
                } else {
                    const float* rr = resid + (size_t)row * N + col;
                    *(float2*)(C + (size_t)row * N + col) =
                        make_float2(d0 + bias[col] + rr[0], d1 + bias[col + 1] + rr[1]);
                }
            }
        }
    }
}

// ---------------- layernorm -> bf16 hi/lo split output ----------------
__global__ __launch_bounds__(256) void ln_bf_kernel(
    const float* __restrict__ x, const float* __restrict__ w,
    const float* __restrict__ b, __nv_bfloat16* __restrict__ hi,
    __nv_bfloat16* __restrict__ lo)
{
    __shared__ float sh[8];
    const int tok = blockIdx.x;
    const float* xi = x + (size_t)tok * D_MODEL;
    float v[3];
    #pragma unroll
    for (int i = 0; i < 3; i++) v[i] = xi[threadIdx.x + i * 256];
    float s = v[0] + v[1] + v[2];
    s = block_sum_256(s, sh);
    const float mu = s * (1.0f / D_MODEL);
    float c[3], sq = 0.0f;
    #pragma unroll
    for (int i = 0; i < 3; i++) { c[i] = v[i] - mu; sq += c[i] * c[i]; }
    sq = block_sum_256(sq, sh);
    const float rstd = rsqrtf(sq * (1.0f / D_MODEL) + EPS);
    #pragma unroll
    for (int i = 0; i < 3; i++) {
        int idx = threadIdx.x + i * 256;
        float o = c[i] * rstd * w[idx] + b[idx];
        __nv_bfloat16 h = __float2bfloat16(o);
        hi[(size_t)tok * D_MODEL + idx] = h;
        lo[(size_t)tok * D_MODEL + idx] = __float2bfloat16(o - __bfloat162float(h));
    }
}

// ---------------- dt preprocessing ----------------
__global__ __launch_bounds__(256) void dt_kernel(
    const float* __restrict__ zx, const float* __restrict__ dt_bias,
    const float* __restrict__ A_log, float* __restrict__ dt_sp, float* __restrict__ dA)
{
    int idx = blockIdx.x * 256 + threadIdx.x;
    if (idx >= NTOK * NHEADS) return;
    int h = idx % NHEADS;
    int tok = idx / NHEADS;
    float v = zx[(size_t)tok * D_IN_PROJ + 3200 + h];
    float sp = softplusf_(v + dt_bias[h]);
    dt_sp[idx] = sp;
    dA[idx] = __expf(-__expf(A_log[h]) * sp);
}

// ---------------- conv1d (+bias, silu), both directions ----------------
__global__ __launch_bounds__(256) void conv_kernel(
    const float* __restrict__ zx, const float* __restrict__ conv_w,
    const float* __restrict__ conv_b, float* __restrict__ out)
{
    long long idx = (long long)blockIdx.x * 256 + threadIdx.x;
    const long long total = 2LL * NTOK * CONV_DIM;
    if (idx >= total) return;
    int c = (int)(idx % CONV_DIM);
    long long r = idx / CONV_DIM;
    int t = (int)(r % SEQ);
    r /= SEQ;
    int b = (int)(r % BSZ);
    int dir = (int)(r / BSZ);
    const float4 w = *(const float4*)(conv_w + (size_t)c * 4);
    const float* base = zx + ((size_t)b * SEQ) * D_IN_PROJ + D_INNER + c;
    float acc = 0.0f;
    if (dir == 0) {
        if (t >= 3) acc += w.x * base[(size_t)(t - 3) * D_IN_PROJ];
        if (t >= 2) acc += w.y * base[(size_t)(t - 2) * D_IN_PROJ];
        if (t >= 1) acc += w.z * base[(size_t)(t - 1) * D_IN_PROJ];
        acc += w.w * base[(size_t)t * D_IN_PROJ];
    } else {
        if (t + 3 < SEQ) acc += w.x * base[(size_t)(t + 3) * D_IN_PROJ];
        if (t + 2 < SEQ) acc += w.y * base[(size_t)(t + 2) * D_IN_PROJ];
        if (t + 1 < SEQ) acc += w.z * base[(size_t)(t + 1) * D_IN_PROJ];
        acc += w.w * base[(size_t)t * D_IN_PROJ];
    }
    acc += conv_b[c];
    out[idx] = siluf_(acc);
}

// ---------------- SSM scan: 1 block / (head,batch,dir); 128 threads ----------
__global__ __launch_bounds__(128) void scan_kernel(
    const float* __restrict__ conv, const float* __restrict__ dt_sp,
    const float* __restrict__ dA_g, const float* __restrict__ D_param,
    float* __restrict__ y_out)
{
    const int hd  = blockIdx.x;
    const int b   = blockIdx.y;
    const int dir = blockIdx.z;
    const int tid = threadIdx.x;
    const int p   = tid >> 1;
    const int g   = tid & 1;
    const float Dh = D_param[hd];

    float h[32];
    #pragma unroll
    for (int n = 0; n < 32; n++) h[n] = 0.0f;

    __shared__ __align__(16) float Bs[2][64];
    __shared__ __align__(16) float Cs[2][64];

    const size_t seq_base = (size_t)(dir * BSZ + b) * SEQ;

    float pBC, pX, pDT, pDA;
    {
        const int s0 = dir ? (SEQ - 1) : 0;
        const float* row = conv + (seq_base + s0) * CONV_DIM;
        pBC = row[D_INNER + g * D_STATE + p];
        pX  = row[hd * HEADDIM + p];
        const int th = (b * SEQ + s0) * NHEADS + hd;
        pDT = dt_sp[th];
        pDA = dA_g[th];
    }

    for (int step = 0; step < SEQ; step++) {
        const int buf = step & 1;
        const int s = dir ? (SEQ - 1 - step) : step;

        if (g == 0) Bs[buf][p] = pBC;
        else        Cs[buf][p] = pBC;
        const float xv  = pX;
        const float dtv = pDT;
        const float dav = pDA;
        __syncthreads();

        {
            const int sn = (step + 1 < SEQ) ? step + 1 : step;
            const int ss = dir ? (SEQ - 1 - sn) : sn;
            const float* row = conv + (seq_base + ss) * CONV_DIM;
            pBC = row[D_INNER + g * D_STATE + p];
            pX  = row[hd * HEADDIM + p];
            const int th = (b * SEQ + ss) * NHEADS + hd;
            pDT = dt_sp[th];
            pDA = dA_g[th];
        }

        const float coeff = dtv * xv;
        const float4* B4 = (const float4*)(Bs[buf] + g * 32);
        const float4* C4 = (const float4*)(Cs[buf] + g * 32);
        float a0 = 0.f, a1 = 0.f, a2 = 0.f, a3 = 0.f;
        #pragma unroll
        for (int q = 0; q < 8; q++) {
            float4 bb = B4[q];
            float4 cc = C4[q];
            h[4*q+0] = fmaf(dav, h[4*q+0], coeff * bb.x);  a0 = fmaf(h[4*q+0], cc.x, a0);
            h[4*q+1] = fmaf(dav, h[4*q+1], coeff * bb.y);  a1 = fmaf(h[4*q+1], cc.y, a1);
            h[4*q+2] = fmaf(dav, h[4*q+2], coeff * bb.z);  a2 = fmaf(h[4*q+2], cc.z, a2);
            h[4*q+3] = fmaf(dav, h[4*q+3], coeff * bb.w);  a3 = fmaf(h[4*q+3], cc.w, a3);
        }
        float acc = (a0 + a1) + (a2 + a3);
        acc += __shfl_xor_sync(0xffffffffu, acc, 1);
        if (!g) {
            y_out[(seq_base + s) * D_INNER + hd * HEADDIM + p] = acc + Dh * xv;
        }
    }
}

// ---------------- gate + RMSNorm -> bf16 hi/lo split ----------------
__global__ __launch_bounds__(256) void gate_bf_kernel(
    const float* __restrict__ y, const float* __restrict__ zx,
    const float* __restrict__ norm_w, __nv_bfloat16* __restrict__ hi,
    __nv_bfloat16* __restrict__ lo)
{
    __shared__ float sh[8];
    const int t = blockIdx.x;
    const int b = blockIdx.y;
    const size_t tok = (size_t)b * SEQ + t;
    const float* zrow = zx + tok * D_IN_PROJ;
    const float* yf = y + tok * D_INNER;
    const float* yb = y + ((size_t)BSZ * SEQ + tok) * D_INNER;

    float gf[6], gb[6];
    float sf = 0.0f, sb = 0.0f;
    #pragma unroll
    for (int i = 0; i < 6; i++) {
        int c = threadIdx.x + i * 256;
        float g = siluf_(zrow[c]);
        gf[i] = yf[c] * g;  sf += gf[i] * gf[i];
        gb[i] = yb[c] * g;  sb += gb[i] * gb[i];
    }
    sf = block_sum_256(sf, sh);
    sb = block_sum_256(sb, sh);
    const float scf = rsqrtf(sf * (1.0f / D_INNER) + EPS);
    const float scb = rsqrtf(sb * (1.0f / D_INNER) + EPS);
    #pragma unroll
    for (int i = 0; i < 6; i++) {
        int c = threadIdx.x + i * 256;
        float o = (gf[i] * scf + gb[i] * scb) * norm_w[c];
        __nv_bfloat16 h = __float2bfloat16(o);
        hi[tok * D_INNER + c] = h;
        lo[tok * D_INNER + c] = __float2bfloat16(o - __bfloat162float(h));
    }
}

// ---------------- launch ----------------
extern "C" void kernel_launch(void* const* d_in, const int* in_sizes, int n_in,
                              void* d_out, int out_size)
{
    const float* x          = (const float*)d_in[0];
    const float* in_proj_w  = (const float*)d_in[1];
    const float* conv_w     = (const float*)d_in[2];
    const float* conv_b     = (const float*)d_in[3];
    const float* dt_bias    = (const float*)d_in[4];
    const float* A_log      = (const float*)d_in[5];
    const float* D_param    = (const float*)d_in[6];
    const float* norm_w     = (const float*)d_in[7];
    const float* out_proj_w = (const float*)d_in[8];
    const float* ln1_w      = (const float*)d_in[9];
    const float* ln1_b      = (const float*)d_in[10];
    const float* ln2_w      = (const float*)d_in[11];
    const float* ln2_b      = (const float*)d_in[12];
    const float* ff_w1      = (const float*)d_in[13];
    const float* ff_b1      = (const float*)d_in[14];
    const float* ff_w2      = (const float*)d_in[15];
    const float* ff_b2      = (const float*)d_in[16];
    float* out = (float*)d_out;

    float *p_zx, *p_dt, *p_dA, *p_conv, *p_y, *p_mp;
    __nv_bfloat16 *p_w1h, *p_w1l, *p_w2h, *p_w2l, *p_w3h, *p_w3l, *p_w4h, *p_w4l;
    __nv_bfloat16 *p_a0h, *p_a0l, *p_a1h, *p_a1l;
    cudaGetSymbolAddress((void**)&p_zx,   g_zx);
    cudaGetSymbolAddress((void**)&p_dt,   g_dt);
    cudaGetSymbolAddress((void**)&p_dA,   g_dA);
    cudaGetSymbolAddress((void**)&p_conv, g_conv);
    cudaGetSymbolAddress((void**)&p_y,    g_y);
    cudaGetSymbolAddress((void**)&p_mp,   g_mp);
    cudaGetSymbolAddress((void**)&p_w1h,  g_w1h);  cudaGetSymbolAddress((void**)&p_w1l, g_w1l);
    cudaGetSymbolAddress((void**)&p_w2h,  g_w2h);  cudaGetSymbolAddress((void**)&p_w2l, g_w2l);
    cudaGetSymbolAddress((void**)&p_w3h,  g_w3h);  cudaGetSymbolAddress((void**)&p_w3l, g_w3l);
    cudaGetSymbolAddress((void**)&p_w4h,  g_w4h);  cudaGetSymbolAddress((void**)&p_w4l, g_w4l);
    cudaGetSymbolAddress((void**)&p_a0h,  g_a0h);  cudaGetSymbolAddress((void**)&p_a0l, g_a0l);
    cudaGetSymbolAddress((void**)&p_a1h,  g_a1h);  cudaGetSymbolAddress((void**)&p_a1l, g_a1l);

    // smem opt-in (host-side attribute set; idempotent)
    cudaFuncSetAttribute(mma_gemm_kernel<0>,   cudaFuncAttributeMaxDynamicSharedMemorySize, 81920);
    cudaFuncSetAttribute(mma_gemm_kernel<1>,   cudaFuncAttributeMaxDynamicSharedMemorySize, 81920);
    cudaFuncSetAttribute(mma_gemm64_kernel<0>, cudaFuncAttributeMaxDynamicSharedMemorySize, 61440);
    cudaFuncSetAttribute(mma_gemm64_kernel<2>, cudaFuncAttributeMaxDynamicSharedMemorySize, 61440);

    // 0) fused weight splits (1 launch)
    convw4_kernel<<<(CW_TOTAL + 255) / 256, 256>>>(
        in_proj_w, out_proj_w, ff_w1, ff_w2,
        p_w1h, p_w1l, p_w2h, p_w2l, p_w3h, p_w3l, p_w4h, p_w4l);

    // 1) LN1 -> a0 (hi/lo)
    ln_bf_kernel<<<NTOK, 256>>>(x, ln1_w, ln1_b, p_a0h, p_a0l);
    // 2) in_proj (128x128 tiles, 2 CTAs/SM)
    mma_gemm_kernel<0><<<dim3(NPAD_INPROJ/128, NTOK/128), 256, 81920>>>(
        p_a0h, p_a0l, p_w1h, p_w1l, nullptr, p_zx, nullptr, nullptr,
        NTOK, D_IN_PROJ, D_MODEL);
    // 3) dt
    dt_kernel<<<(NTOK * NHEADS + 255) / 256, 256>>>(p_zx, dt_bias, A_log, p_dt, p_dA);
    // 4) conv + silu
    {
        long long total = 2LL * NTOK * CONV_DIM;
        conv_kernel<<<(unsigned)((total + 255) / 256), 256>>>(p_zx, conv_w, conv_b, p_conv);
    }
    // 5) scan
    scan_kernel<<<dim3(NHEADS, BSZ, 2), 128>>>(p_conv, p_dt, p_dA, D_param, p_y);
    // 6) gate + rmsnorm -> a0 (hi/lo)
    gate_bf_kernel<<<dim3(SEQ, BSZ), 256>>>(p_y, p_zx, norm_w, p_a0h, p_a0l);
    // 7) out_proj (64x64 tiles, 192 CTAs)
    mma_gemm64_kernel<0><<<dim3(D_MODEL/64, NTOK/64), 128, 61440>>>(
        p_a0h, p_a0l, p_w2h, p_w2l, nullptr, nullptr, p_mp,
        NTOK, D_MODEL, D_INNER);
    // 8) LN2 -> a0 (hi/lo)
    ln_bf_kernel<<<NTOK, 256>>>(p_mp, ln2_w, ln2_b, p_a0h, p_a0l);
    // 9) FFN1: gelu(m@W1+b1) -> a1 (hi/lo fused split epilogue)
    mma_gemm_kernel<1><<<dim3(D_FF/128, NTOK/128), 256, 81920>>>(
        p_a0h, p_a0l, p_w3h, p_w3l, ff_b1, nullptr, p_a1h, p_a1l,
        NTOK, D_FF, D_MODEL);
    // 10) FFN2 + bias + residual -> d_out (64x64 tiles)
    mma_gemm64_kernel<2><<<dim3(D_MODEL/64, NTOK/64), 128, 61440>>>(
        p_a1h, p_a1l, p_w4h, p_w4l, ff_b2, x, out,
        NTOK, D_MODEL, D_FF);
}